// round 13
// baseline (speedup 1.0000x reference)
#include <cuda_runtime.h>
#include <cuda_bf16.h>
#include <mma.h>
#include <math.h>
#include <cstdint>

using namespace nvcuda;

#define BATCH 2048
#define SEQ   80
#define UNITS 512
#define EMB   100
#define EMBP  128
#define BT    (BATCH*SEQ)
#define THREADS 512

// ---- scan tiling ----
#define BM 128
#define BN 64
#define NBLK 128                 // 16 m-groups x 8 n-tiles
#define LDSU 72
#define LDSA 72
#define LDSC 68
#define ABUF 18432               // 128*72*2
#define SM_U    0                // 73728
#define SM_W    73728            // 73728
#define SM_A    147456           // 3*18432 = 55296 (sC f32 aliases buf0/1)
#define SM_BIAS 202752
#define SCAN_SMEM 203008

// ---- layer-0 bulk tiling ----
#define GBN 128
#define LDBB 136
#define LDBA 72
#define LDBC 132
#define BULK_ABUF 18432
#define GM_B 0
#define GM_A 139264
#define BULK_SMEM 194560

// ---------------- persistent device scratch (TIME-MAJOR: [t][batch][.]) ----------------
__device__ __nv_bfloat16 g_X[(size_t)BT * EMBP];
__device__ __nv_bfloat16 g_Z[(size_t)BT * UNITS];   // layer-0 Z, standard layout
__device__ __nv_bfloat16 g_Zp[(size_t)SEQ * NBLK * THREADS * 16];  // fragment-native Z
__device__ __nv_bfloat16 g_H[(size_t)BT * UNITS];
__device__ __nv_bfloat16 g_W1p[EMBP * UNITS];
__device__ __nv_bfloat16 g_W[3][UNITS * UNITS];     // g_W[l] = Wm[l+1]
__device__ __nv_bfloat16 g_U[4][UNITS * UNITS];
__device__ unsigned int  g_flg[16 * 8 * 16];        // per (mg,nb) monotonic flag, 64B stride

// ---------------- helpers ----------------
__device__ __forceinline__ uint32_t smem_u32(const void* p) {
    uint32_t a;
    asm("{ .reg .u64 t; cvta.to.shared.u64 t, %1; cvt.u32.u64 %0, t; }" : "=r"(a) : "l"(p));
    return a;
}
__device__ __forceinline__ void cp16(uint32_t dst, const void* src) {
    asm volatile("cp.async.cg.shared.global [%0], [%1], 16;" :: "r"(dst), "l"(src));
}
#define CP_COMMIT() asm volatile("cp.async.commit_group;" ::: "memory")
#define CP_WAIT1()  asm volatile("cp.async.wait_group 1;" ::: "memory")
#define CP_WAIT0()  asm volatile("cp.async.wait_group 0;" ::: "memory")

__device__ __forceinline__ void arrive_release(unsigned int* p) {
    asm volatile("red.release.gpu.global.add.u32 [%0], %1;" :: "l"(p), "r"(1u) : "memory");
}
__device__ __forceinline__ unsigned ld_acquire(const unsigned int* p) {
    unsigned v;
    asm volatile("ld.acquire.gpu.global.u32 %0, [%1];" : "=r"(v) : "l"(p) : "memory");
    return v;
}
__device__ __forceinline__ void wait_flag(const unsigned int* p, unsigned tgt) {
    while (ld_acquire(p) < tgt) { }
}
__device__ __forceinline__ float tanhfast(float x) {
    float y;
    asm("tanh.approx.f32 %0, %1;" : "=f"(y) : "f"(x));
    return y;
}

// ---------------- embed + weight prep ----------------
__global__ void embed_kernel(const int* __restrict__ tokens, const float* __restrict__ emb) {
    size_t idx = (size_t)blockIdx.x * blockDim.x + threadIdx.x;
    if (idx >= (size_t)BT * EMBP) return;
    size_t row = idx >> 7;          // t*BATCH + b
    int col = (int)(idx & 127);
    int t = (int)(row >> 11);
    int b = (int)(row & 2047);
    int tok = tokens[(size_t)b * SEQ + t];
    float v = (col < EMB) ? emb[(size_t)tok * EMB + col] : 0.f;
    g_X[idx] = __float2bfloat16(v);
}

__global__ void prep_all(const float* __restrict__ W1, const float* __restrict__ W2,
                         const float* __restrict__ W3, const float* __restrict__ W4,
                         const float* __restrict__ U1, const float* __restrict__ U2,
                         const float* __restrict__ U3, const float* __restrict__ U4) {
    int y = blockIdx.y;
    int idx = blockIdx.x * blockDim.x + threadIdx.x;
    if (y == 0) {
        if (idx < EMBP * UNITS) {
            int k = idx >> 9, n = idx & 511;
            g_W1p[idx] = __float2bfloat16(k < EMB ? W1[k * UNITS + n] : 0.f);
        }
    } else if (y <= 3) {
        const float* s = (y == 1) ? W2 : (y == 2) ? W3 : W4;
        if (idx < UNITS * UNITS) g_W[y - 1][idx] = __float2bfloat16(s[idx]);
    } else {
        const float* s = (y == 4) ? U1 : (y == 5) ? U2 : (y == 6) ? U3 : U4;
        if (idx < UNITS * UNITS) g_U[y - 4][idx] = __float2bfloat16(s[idx]);
    }
}

// ---------------- layer-0 bulk GEMM: g_Z = X @ W1p ----------------
__global__ __launch_bounds__(THREADS, 1) void gemm0() {
    extern __shared__ __align__(16) unsigned char smraw[];
    __nv_bfloat16* sB = (__nv_bfloat16*)(smraw + GM_B);
    float*         sC = (float*)(smraw + GM_B);

    const __nv_bfloat16* Ag = g_X;
    const __nv_bfloat16* Bg = g_W1p;
    const int K = EMBP, aStride = EMBP, KC = 2;

    const int n0 = blockIdx.x * GBN;
    const int m0 = blockIdx.y * BM;
    const int tid = threadIdx.x;
    const int wid = tid >> 5;
    const int wm = wid & 3, wn = wid >> 2;

    const uint32_t sbase = smem_u32(smraw);
    const uint32_t aBase = sbase + GM_A;

    for (int i = tid; i < K * 16; i += THREADS) {
        int r = i >> 4, c = i & 15;
        cp16(sbase + GM_B + r * (LDBB * 2) + c * 16, Bg + (size_t)r * UNITS + n0 + c * 8);
    }
    {
        #pragma unroll
        for (int j = 0; j < 2; j++) {
            int i = tid + j * THREADS;
            int r = i >> 3, c = i & 7;
            cp16(aBase + r * (LDBA * 2) + c * 16, Ag + (size_t)(m0 + r) * aStride + c * 8);
        }
    }
    CP_COMMIT();

    wmma::fragment<wmma::accumulator, 16, 16, 16, float> acc[2][2];
    #pragma unroll
    for (int i = 0; i < 2; i++)
        #pragma unroll
        for (int j = 0; j < 2; j++) wmma::fill_fragment(acc[i][j], 0.f);

    int buf = 0;
    for (int kc = 0; kc < KC; kc++) {
        if (kc + 1 < KC) {
            int nb = buf + 1;
            #pragma unroll
            for (int j = 0; j < 2; j++) {
                int i = tid + j * THREADS;
                int r = i >> 3, c = i & 7;
                cp16(aBase + nb * BULK_ABUF + r * (LDBA * 2) + c * 16,
                     Ag + (size_t)(m0 + r) * aStride + (kc + 1) * 64 + c * 8);
            }
            CP_COMMIT();
            CP_WAIT1();
        } else {
            CP_WAIT0();
        }
        __syncthreads();

        const __nv_bfloat16* sA = (const __nv_bfloat16*)(smraw + GM_A + buf * BULK_ABUF);
        #pragma unroll
        for (int kk = 0; kk < 64; kk += 16) {
            wmma::fragment<wmma::matrix_a, 16, 16, 16, __nv_bfloat16, wmma::row_major> a0, a1;
            wmma::fragment<wmma::matrix_b, 16, 16, 16, __nv_bfloat16, wmma::row_major> b0, b1;
            wmma::load_matrix_sync(a0, sA + (wm * 32) * LDBA + kk, LDBA);
            wmma::load_matrix_sync(a1, sA + (wm * 32 + 16) * LDBA + kk, LDBA);
            wmma::load_matrix_sync(b0, sB + (kc * 64 + kk) * LDBB + wn * 32, LDBB);
            wmma::load_matrix_sync(b1, sB + (kc * 64 + kk) * LDBB + wn * 32 + 16, LDBB);
            wmma::mma_sync(acc[0][0], a0, b0, acc[0][0]);
            wmma::mma_sync(acc[0][1], a0, b1, acc[0][1]);
            wmma::mma_sync(acc[1][0], a1, b0, acc[1][0]);
            wmma::mma_sync(acc[1][1], a1, b1, acc[1][1]);
        }
        buf++;
    }
    __syncthreads();

    #pragma unroll
    for (int i = 0; i < 2; i++)
        #pragma unroll
        for (int j = 0; j < 2; j++)
            wmma::store_matrix_sync(&sC[(wm * 32 + i * 16) * LDBC + wn * 32 + j * 16],
                                    acc[i][j], LDBC, wmma::mem_row_major);
    __syncthreads();

    {
        const int erow = tid >> 2;
        const int ecb  = (tid & 3) * 32;
        const float* s = &sC[erow * LDBC + ecb];
        __nv_bfloat162 p[16];
        #pragma unroll
        for (int q = 0; q < 16; q++) p[q] = __floats2bfloat162_rn(s[2*q], s[2*q+1]);
        __nv_bfloat16* dst = g_Z + (size_t)(m0 + erow) * UNITS + n0 + ecb;
        #pragma unroll
        for (int q = 0; q < 4; q++)
            *(uint4*)(dst + q * 8) = *(uint4*)&p[q * 4];
    }
}

// ---------------- fused persistent scan: per-producer flags, chunk-wise dataflow ----------------
__global__ __launch_bounds__(THREADS, 1)
void scan_layer(int layer, const float* __restrict__ bias, int hasZ, int zPerm, unsigned lBase) {
    extern __shared__ __align__(16) unsigned char smraw[];
    __nv_bfloat16* sU = (__nv_bfloat16*)(smraw + SM_U);
    __nv_bfloat16* sW = (__nv_bfloat16*)(smraw + SM_W);
    float*         sC = (float*)(smraw + SM_A);
    float*         sBias = (float*)(smraw + SM_BIAS);
    const uint32_t aBase = smem_u32(smraw) + SM_A;

    const int tid = threadIdx.x;
    const int wid = tid >> 5;
    const int bid = blockIdx.x;
    const int nb = bid & 7;
    const int mg = bid >> 3;
    const int n0 = nb * BN;
    const int m0 = mg * BM;
    const int wm = wid & 3, wn = wid >> 2;

    unsigned int* myFlag = &g_flg[(mg * 8 + nb) * 16];
    const unsigned int* grpFlags = &g_flg[(mg * 8) * 16];

    // stage U and (if hasZ) Wnext
    {
        const __nv_bfloat16* U = g_U[layer];
        #pragma unroll
        for (int j = 0; j < 8; j++) {
            int i = tid + j * THREADS;
            int r = i >> 3, c = i & 7;
            *(uint4*)&sU[r * LDSU + c * 8] = *(const uint4*)(U + (size_t)r * UNITS + n0 + c * 8);
        }
        if (hasZ) {
            const __nv_bfloat16* W = g_W[layer];
            #pragma unroll
            for (int j = 0; j < 8; j++) {
                int i = tid + j * THREADS;
                int r = i >> 3, c = i & 7;
                *(uint4*)&sW[r * LDSU + c * 8] = *(const uint4*)(W + (size_t)r * UNITS + n0 + c * 8);
            }
        }
        if (tid < BN) sBias[tid] = bias[n0 + tid];
    }
    __syncthreads();

    const int erow = (wid & 3) * 32 + (tid & 31);
    const int ecb  = (wid >> 2) * 16;
    const int bRow = m0 + erow;
    const int lane = tid & 31;
    const int c0 = (lane & 3) * 2;
    const int colg = n0 + wn * 16 + c0;
    const float fb0 = bias[colg],     fb1 = bias[colg + 1];
    const float fb8 = bias[colg + 8], fb9 = bias[colg + 9];

    const int itMax = hasZ ? SEQ : (SEQ - 1);

    for (int it = 0; it <= itMax; it++) {
        const bool doRec = (it < SEQ);
        const bool doZ   = (hasZ && it >= 1);

        if (it == 0) {
            // h_0 = tanh(Z_0 + b)
            if (zPerm) {
                const uint4* p = (const uint4*)(g_Zp + ((size_t)bid * THREADS + tid) * 16);
                uint4 q0 = p[0], q1 = p[1];
                __nv_bfloat16 zf[16];
                *(uint4*)&zf[0] = q0; *(uint4*)&zf[8] = q1;
                const int r0 = lane >> 2;
                #pragma unroll
                for (int f = 0; f < 2; f++) {
                    int rowb = m0 + wm * 32 + f * 16;
                    #pragma unroll
                    for (int e = 0; e < 4; e++) {
                        int row = rowb + r0 + ((e & 1) ? 8 : 0);
                        int col = colg + ((e & 2) ? 8 : 0);
                        float v0 = __bfloat162float(zf[f * 8 + e * 2]);
                        float v1 = __bfloat162float(zf[f * 8 + e * 2 + 1]);
                        float blo = (e & 2) ? fb8 : fb0, bhi = (e & 2) ? fb9 : fb1;
                        __nv_bfloat162 o = __floats2bfloat162_rn(tanhfast(v0 + blo), tanhfast(v1 + bhi));
                        *(__nv_bfloat162*)(g_H + (size_t)row * UNITS + col) = o;
                    }
                }
            } else {
                size_t eidx = (size_t)bRow * UNITS + n0 + ecb;
                uint4 z0 = *(const uint4*)(g_Z + eidx);
                uint4 z1 = *(const uint4*)(g_Z + eidx + 8);
                __nv_bfloat162 zb[8];
                *(uint4*)&zb[0] = z0; *(uint4*)&zb[4] = z1;
                __nv_bfloat162 o[8];
                #pragma unroll
                for (int c = 0; c < 8; c++)
                    o[c] = __floats2bfloat162_rn(tanhfast(__low2float(zb[c])  + sBias[ecb + 2*c]),
                                                 tanhfast(__high2float(zb[c]) + sBias[ecb + 2*c + 1]));
                __nv_bfloat16* dst = g_H + eidx;
                *(uint4*)dst       = *(uint4*)&o[0];
                *(uint4*)(dst + 8) = *(uint4*)&o[4];
            }
            __syncthreads();                      // all h_0 stores done block-wide
            if (tid == 0) arrive_release(myFlag); // flag value -> lBase + 1
            continue;
        }

        // A = h_{it-1} slab; chunk kc produced by n-block kc of this m-group
        const __nv_bfloat16* A = g_H + (size_t)(it - 1) * BATCH * UNITS + (size_t)m0 * UNITS;
        const unsigned ftgt = lBase + (unsigned)it;   // flag >= lBase+it means h_{it-1} ready

        // prologue: chunks 0,1 (poll producer flags first; all threads)
        wait_flag(&grpFlags[0 * 16], ftgt);
        #pragma unroll
        for (int j = 0; j < 2; j++) {
            int i = tid + j * THREADS;
            int r = i >> 3, c = i & 7;
            cp16(aBase + 0 * ABUF + r * (LDSA * 2) + c * 16,
                 A + (size_t)r * UNITS + 0 * 64 + c * 8);
        }
        CP_COMMIT();
        wait_flag(&grpFlags[1 * 16], ftgt);
        #pragma unroll
        for (int j = 0; j < 2; j++) {
            int i = tid + j * THREADS;
            int r = i >> 3, c = i & 7;
            cp16(aBase + 1 * ABUF + r * (LDSA * 2) + c * 16,
                 A + (size_t)r * UNITS + 1 * 64 + c * 8);
        }
        CP_COMMIT();

        // own-Z prefetch
        uint4 zp0, zp1;          // fragment-native
        uint4 zr0, zr1;          // standard (layer 0)
        if (doRec) {
            if (zPerm) {
                const uint4* p = (const uint4*)(g_Zp + (((size_t)it * NBLK + bid) * THREADS + tid) * 16);
                zp0 = p[0]; zp1 = p[1];
            } else {
                const uint4* zp = (const uint4*)(g_Z + ((size_t)it * BATCH + bRow) * UNITS + n0 + ecb);
                zr0 = zp[0]; zr1 = zp[1];
            }
        }

        wmma::fragment<wmma::accumulator, 16, 16, 16, float> accR[2], accZ[2];
        if (doRec) { wmma::fill_fragment(accR[0], 0.f); wmma::fill_fragment(accR[1], 0.f); }
        if (doZ)   { wmma::fill_fragment(accZ[0], 0.f); wmma::fill_fragment(accZ[1], 0.f); }

        for (int kc = 0; kc < 8; kc++) {
            // poll next producer while current chunk's copies drain
            if (kc + 2 < 8) wait_flag(&grpFlags[(kc + 2) * 16], ftgt);
            if (kc < 7) CP_WAIT1(); else CP_WAIT0();
            __syncthreads();                      // chunk kc fully landed block-wide
            if (kc + 2 < 8) {
                int nbuf = (kc + 2) % 3;
                #pragma unroll
                for (int j = 0; j < 2; j++) {
                    int i = tid + j * THREADS;
                    int r = i >> 3, c = i & 7;
                    cp16(aBase + nbuf * ABUF + r * (LDSA * 2) + c * 16,
                         A + (size_t)r * UNITS + (kc + 2) * 64 + c * 8);
                }
                CP_COMMIT();
            }
            const __nv_bfloat16* sA  = (const __nv_bfloat16*)(smraw + SM_A + (kc % 3) * ABUF);
            const __nv_bfloat16* sUw = sU + (kc * 64) * LDSU + wn * 16;
            const __nv_bfloat16* sWw = sW + (kc * 64) * LDSU + wn * 16;
            #pragma unroll
            for (int kk = 0; kk < 64; kk += 16) {
                wmma::fragment<wmma::matrix_a, 16, 16, 16, __nv_bfloat16, wmma::row_major> a0, a1;
                wmma::load_matrix_sync(a0, sA + (wm * 32) * LDSA + kk, LDSA);
                wmma::load_matrix_sync(a1, sA + (wm * 32 + 16) * LDSA + kk, LDSA);
                if (doRec) {
                    wmma::fragment<wmma::matrix_b, 16, 16, 16, __nv_bfloat16, wmma::row_major> bU;
                    wmma::load_matrix_sync(bU, sUw + kk * LDSU, LDSU);
                    wmma::mma_sync(accR[0], a0, bU, accR[0]);
                    wmma::mma_sync(accR[1], a1, bU, accR[1]);
                }
                if (doZ) {
                    wmma::fragment<wmma::matrix_b, 16, 16, 16, __nv_bfloat16, wmma::row_major> bW;
                    wmma::load_matrix_sync(bW, sWw + kk * LDSU, LDSU);
                    wmma::mma_sync(accZ[0], a0, bW, accZ[0]);
                    wmma::mma_sync(accZ[1], a1, bW, accZ[1]);
                }
            }
        }
        __syncthreads();   // MMA done; A buffers (sC alias) free

        if (doRec) {
            if (zPerm) {
                __nv_bfloat16 zf[16];
                *(uint4*)&zf[0] = zp0;
                *(uint4*)&zf[8] = zp1;
                #pragma unroll
                for (int e = 0; e < 8; e++) {
                    accR[0].x[e] += __bfloat162float(zf[e]);
                    accR[1].x[e] += __bfloat162float(zf[8 + e]);
                }
            }
            wmma::store_matrix_sync(&sC[(wm * 32) * LDSC + wn * 16],      accR[0], LDSC, wmma::mem_row_major);
            wmma::store_matrix_sync(&sC[(wm * 32 + 16) * LDSC + wn * 16], accR[1], LDSC, wmma::mem_row_major);
            __syncthreads();
            const float* s = &sC[erow * LDSC + ecb];
            __nv_bfloat162 o[8];
            size_t eidx = ((size_t)it * BATCH + bRow) * UNITS + n0 + ecb;
            if (zPerm) {
                #pragma unroll
                for (int c = 0; c < 8; c++)
                    o[c] = __floats2bfloat162_rn(
                        tanhfast(s[2*c]     + sBias[ecb + 2*c]),
                        tanhfast(s[2*c + 1] + sBias[ecb + 2*c + 1]));
            } else {
                __nv_bfloat162 zb[8];
                *(uint4*)&zb[0] = zr0; *(uint4*)&zb[4] = zr1;
                #pragma unroll
                for (int c = 0; c < 8; c++)
                    o[c] = __floats2bfloat162_rn(
                        tanhfast(s[2*c]     + __low2float(zb[c])  + sBias[ecb + 2*c]),
                        tanhfast(s[2*c + 1] + __high2float(zb[c]) + sBias[ecb + 2*c + 1]));
            }
            __nv_bfloat16* dst = g_H + eidx;
            *(uint4*)dst       = *(uint4*)&o[0];
            *(uint4*)(dst + 8) = *(uint4*)&o[4];

            // publish h_it: all stores issued block-wide, then release
            __syncthreads();
            if (tid == 0) arrive_release(myFlag);   // flag -> lBase + it + 1
        }

        if (doZ) {
            // Z^{l+1}_{it-1}: fragment-native, fully coalesced
            __nv_bfloat16 zo[16];
            #pragma unroll
            for (int e = 0; e < 8; e++) {
                zo[e]     = __float2bfloat16(accZ[0].x[e]);
                zo[8 + e] = __float2bfloat16(accZ[1].x[e]);
            }
            uint4* dst = (uint4*)(g_Zp + (((size_t)(it - 1) * NBLK + bid) * THREADS + tid) * 16);
            dst[0] = *(uint4*)&zo[0];
            dst[1] = *(uint4*)&zo[8];
        }
    }
}

// ---------------- head ----------------
__global__ void head(const float* __restrict__ Wo, const float* __restrict__ bo,
                     float* __restrict__ out) {
    int gt = blockIdx.x * blockDim.x + threadIdx.x;
    int w = gt >> 5, lane = gt & 31;
    if (w >= BATCH) return;
    const __nv_bfloat16* h = g_H + ((size_t)(SEQ - 1) * BATCH + w) * UNITS;
    float s = 0.f;
    for (int k = lane; k < UNITS; k += 32)
        s += __bfloat162float(h[k]) * Wo[k];
    #pragma unroll
    for (int o = 16; o; o >>= 1) s += __shfl_xor_sync(0xffffffffu, s, o);
    if (lane == 0) out[w] = 1.f / (1.f + expf(-(s + bo[0])));
}

// ---------------- launch ----------------
extern "C" void kernel_launch(void* const* d_in, const int* in_sizes, int n_in,
                              void* d_out, int out_size) {
    const int*   tokens = (const int*)d_in[0];
    const float* emb    = (const float*)d_in[1];
    const float* Wm[4]  = {(const float*)d_in[2],  (const float*)d_in[5],
                           (const float*)d_in[8],  (const float*)d_in[11]};
    const float* Um[4]  = {(const float*)d_in[3],  (const float*)d_in[6],
                           (const float*)d_in[9],  (const float*)d_in[12]};
    const float* bm[4]  = {(const float*)d_in[4],  (const float*)d_in[7],
                           (const float*)d_in[10], (const float*)d_in[13]};
    const float* Wo = (const float*)d_in[14];
    const float* bo = (const float*)d_in[15];
    float* out = (float*)d_out;

    cudaFuncSetAttribute(gemm0,      cudaFuncAttributeMaxDynamicSharedMemorySize, BULK_SMEM);
    cudaFuncSetAttribute(scan_layer, cudaFuncAttributeMaxDynamicSharedMemorySize, SCAN_SMEM);

    void* flgAddr = nullptr;
    cudaGetSymbolAddress(&flgAddr, g_flg);
    cudaMemsetAsync(flgAddr, 0, 16 * 8 * 16 * sizeof(unsigned int));

    embed_kernel<<<(int)(((size_t)BT * EMBP + 255) / 256), 256>>>(tokens, emb);

    dim3 pg(1024, 8);
    prep_all<<<pg, 256>>>(Wm[0], Wm[1], Wm[2], Wm[3], Um[0], Um[1], Um[2], Um[3]);

    dim3 gin(UNITS / GBN, BT / BM);     // (4, 1280)
    gemm0<<<gin, THREADS, BULK_SMEM>>>();

    for (int l = 0; l < 4; l++) {
        int hasZ = (l < 3) ? 1 : 0;
        int zPerm = (l > 0) ? 1 : 0;
        scan_layer<<<NBLK, THREADS, SCAN_SMEM>>>(l, bm[l], hasZ, zPerm, (unsigned)(l * SEQ));
    }
    head<<<(BATCH * 32 + 255) / 256, 256>>>(Wo, bo, out);
}

// round 14
// speedup vs baseline: 1.1333x; 1.1333x over previous
#include <cuda_runtime.h>
#include <cuda_bf16.h>
#include <mma.h>
#include <math.h>
#include <cstdint>

using namespace nvcuda;

#define BATCH 2048
#define SEQ   80
#define UNITS 512
#define EMB   100
#define EMBP  128
#define BT    (BATCH*SEQ)
#define THREADS 512              // gemm0 / preps
#define STH     256              // scan threads (8 warps, 4x2 of 32x32 tiles)

// ---- scan tiling ----
#define BM 128
#define BN 64
#define NBLK 128                 // 16 m-groups x 8 n-tiles
#define LDSU 72
#define LDSA 72
#define LDSC 68
#define ABUF 18432               // 128*72*2
#define SM_U    0                // 73728
#define SM_W    73728            // 73728
#define SM_A    147456           // 3*18432 = 55296 (sC f32 aliases buf0/1)
#define SM_BIAS 202752
#define SCAN_SMEM 203008

// ---- layer-0 bulk tiling ----
#define GBN 128
#define LDBB 136
#define LDBA 72
#define LDBC 132
#define BULK_ABUF 18432
#define GM_B 0
#define GM_A 139264
#define BULK_SMEM 194560

// ---------------- persistent device scratch (TIME-MAJOR: [t][batch][.]) ----------------
__device__ __nv_bfloat16 g_X[(size_t)BT * EMBP];
__device__ __nv_bfloat16 g_Z[(size_t)BT * UNITS];
__device__ __nv_bfloat16 g_H[(size_t)BT * UNITS];
__device__ __nv_bfloat16 g_W1p[EMBP * UNITS];
__device__ __nv_bfloat16 g_W[3][UNITS * UNITS];     // g_W[l] = Wm[l+1]
__device__ __nv_bfloat16 g_U[4][UNITS * UNITS];
__device__ unsigned int  g_arr[16];

// ---------------- helpers ----------------
__device__ __forceinline__ uint32_t smem_u32(const void* p) {
    uint32_t a;
    asm("{ .reg .u64 t; cvta.to.shared.u64 t, %1; cvt.u32.u64 %0, t; }" : "=r"(a) : "l"(p));
    return a;
}
__device__ __forceinline__ void cp16(uint32_t dst, const void* src) {
    asm volatile("cp.async.cg.shared.global [%0], [%1], 16;" :: "r"(dst), "l"(src));
}
#define CP_COMMIT() asm volatile("cp.async.commit_group;" ::: "memory")
#define CP_WAIT1()  asm volatile("cp.async.wait_group 1;" ::: "memory")
#define CP_WAIT0()  asm volatile("cp.async.wait_group 0;" ::: "memory")

__device__ __forceinline__ void arrive_release(unsigned int* p) {
    asm volatile("red.release.gpu.global.add.u32 [%0], %1;" :: "l"(p), "r"(1u) : "memory");
}
__device__ __forceinline__ unsigned ld_acquire(const unsigned int* p) {
    unsigned v;
    asm volatile("ld.acquire.gpu.global.u32 %0, [%1];" : "=r"(v) : "l"(p) : "memory");
    return v;
}
__device__ __forceinline__ float tanhfast(float x) {
    float y;
    asm("tanh.approx.f32 %0, %1;" : "=f"(y) : "f"(x));
    return y;
}

// ---------------- embed + weight prep ----------------
__global__ void embed_kernel(const int* __restrict__ tokens, const float* __restrict__ emb) {
    size_t idx = (size_t)blockIdx.x * blockDim.x + threadIdx.x;
    if (idx >= (size_t)BT * EMBP) return;
    size_t row = idx >> 7;          // t*BATCH + b
    int col = (int)(idx & 127);
    int t = (int)(row >> 11);
    int b = (int)(row & 2047);
    int tok = tokens[(size_t)b * SEQ + t];
    float v = (col < EMB) ? emb[(size_t)tok * EMB + col] : 0.f;
    g_X[idx] = __float2bfloat16(v);
}

__global__ void prep_all(const float* __restrict__ W1, const float* __restrict__ W2,
                         const float* __restrict__ W3, const float* __restrict__ W4,
                         const float* __restrict__ U1, const float* __restrict__ U2,
                         const float* __restrict__ U3, const float* __restrict__ U4) {
    int y = blockIdx.y;
    int idx = blockIdx.x * blockDim.x + threadIdx.x;
    if (y == 0) {
        if (idx < EMBP * UNITS) {
            int k = idx >> 9, n = idx & 511;
            g_W1p[idx] = __float2bfloat16(k < EMB ? W1[k * UNITS + n] : 0.f);
        }
    } else if (y <= 3) {
        const float* s = (y == 1) ? W2 : (y == 2) ? W3 : W4;
        if (idx < UNITS * UNITS) g_W[y - 1][idx] = __float2bfloat16(s[idx]);
    } else {
        const float* s = (y == 4) ? U1 : (y == 5) ? U2 : (y == 6) ? U3 : U4;
        if (idx < UNITS * UNITS) g_U[y - 4][idx] = __float2bfloat16(s[idx]);
    }
}

// ---------------- layer-0 bulk GEMM: g_Z = X @ W1p ----------------
__global__ __launch_bounds__(THREADS, 1) void gemm0() {
    extern __shared__ __align__(16) unsigned char smraw[];
    __nv_bfloat16* sB = (__nv_bfloat16*)(smraw + GM_B);
    float*         sC = (float*)(smraw + GM_B);

    const __nv_bfloat16* Ag = g_X;
    const __nv_bfloat16* Bg = g_W1p;
    const int K = EMBP, aStride = EMBP, KC = 2;

    const int n0 = blockIdx.x * GBN;
    const int m0 = blockIdx.y * BM;
    const int tid = threadIdx.x;
    const int wid = tid >> 5;
    const int wm = wid & 3, wn = wid >> 2;

    const uint32_t sbase = smem_u32(smraw);
    const uint32_t aBase = sbase + GM_A;

    for (int i = tid; i < K * 16; i += THREADS) {
        int r = i >> 4, c = i & 15;
        cp16(sbase + GM_B + r * (LDBB * 2) + c * 16, Bg + (size_t)r * UNITS + n0 + c * 8);
    }
    {
        #pragma unroll
        for (int j = 0; j < 2; j++) {
            int i = tid + j * THREADS;
            int r = i >> 3, c = i & 7;
            cp16(aBase + r * (LDBA * 2) + c * 16, Ag + (size_t)(m0 + r) * aStride + c * 8);
        }
    }
    CP_COMMIT();

    wmma::fragment<wmma::accumulator, 16, 16, 16, float> acc[2][2];
    #pragma unroll
    for (int i = 0; i < 2; i++)
        #pragma unroll
        for (int j = 0; j < 2; j++) wmma::fill_fragment(acc[i][j], 0.f);

    int buf = 0;
    for (int kc = 0; kc < KC; kc++) {
        if (kc + 1 < KC) {
            int nb = buf + 1;
            #pragma unroll
            for (int j = 0; j < 2; j++) {
                int i = tid + j * THREADS;
                int r = i >> 3, c = i & 7;
                cp16(aBase + nb * BULK_ABUF + r * (LDBA * 2) + c * 16,
                     Ag + (size_t)(m0 + r) * aStride + (kc + 1) * 64 + c * 8);
            }
            CP_COMMIT();
            CP_WAIT1();
        } else {
            CP_WAIT0();
        }
        __syncthreads();

        const __nv_bfloat16* sA = (const __nv_bfloat16*)(smraw + GM_A + buf * BULK_ABUF);
        #pragma unroll
        for (int kk = 0; kk < 64; kk += 16) {
            wmma::fragment<wmma::matrix_a, 16, 16, 16, __nv_bfloat16, wmma::row_major> a0, a1;
            wmma::fragment<wmma::matrix_b, 16, 16, 16, __nv_bfloat16, wmma::row_major> b0, b1;
            wmma::load_matrix_sync(a0, sA + (wm * 32) * LDBA + kk, LDBA);
            wmma::load_matrix_sync(a1, sA + (wm * 32 + 16) * LDBA + kk, LDBA);
            wmma::load_matrix_sync(b0, sB + (kc * 64 + kk) * LDBB + wn * 32, LDBB);
            wmma::load_matrix_sync(b1, sB + (kc * 64 + kk) * LDBB + wn * 32 + 16, LDBB);
            wmma::mma_sync(acc[0][0], a0, b0, acc[0][0]);
            wmma::mma_sync(acc[0][1], a0, b1, acc[0][1]);
            wmma::mma_sync(acc[1][0], a1, b0, acc[1][0]);
            wmma::mma_sync(acc[1][1], a1, b1, acc[1][1]);
        }
        buf++;
    }
    __syncthreads();

    #pragma unroll
    for (int i = 0; i < 2; i++)
        #pragma unroll
        for (int j = 0; j < 2; j++)
            wmma::store_matrix_sync(&sC[(wm * 32 + i * 16) * LDBC + wn * 32 + j * 16],
                                    acc[i][j], LDBC, wmma::mem_row_major);
    __syncthreads();

    {
        const int erow = tid >> 2;
        const int ecb  = (tid & 3) * 32;
        const float* s = &sC[erow * LDBC + ecb];
        __nv_bfloat162 p[16];
        #pragma unroll
        for (int q = 0; q < 16; q++) p[q] = __floats2bfloat162_rn(s[2*q], s[2*q+1]);
        __nv_bfloat16* dst = g_Z + (size_t)(m0 + erow) * UNITS + n0 + ecb;
        #pragma unroll
        for (int q = 0; q < 4; q++)
            *(uint4*)(dst + q * 8) = *(uint4*)&p[q * 4];
    }
}

// ---------------- fused persistent scan: 8 warps, 32x32 warp tiles (R10 flow) ----------------
__global__ __launch_bounds__(STH, 1)
void scan_layer(int layer, const float* __restrict__ bias, int hasZ, unsigned barBase) {
    extern __shared__ __align__(16) unsigned char smraw[];
    __nv_bfloat16* sU = (__nv_bfloat16*)(smraw + SM_U);
    __nv_bfloat16* sW = (__nv_bfloat16*)(smraw + SM_W);
    float*         sC = (float*)(smraw + SM_A);
    float*         sBias = (float*)(smraw + SM_BIAS);
    const uint32_t aBase = smem_u32(smraw) + SM_A;

    const int tid = threadIdx.x;
    const int wid = tid >> 5;
    const int bid = blockIdx.x;
    const int n0 = (bid & 7) * BN;
    const int mg = bid >> 3;
    const int m0 = mg * BM;
    const int wm = wid & 3;          // 4 m-slices of 32
    const int wn = wid >> 2;         // 2 n-slices of 32

    // stage U and (if hasZ) Wnext
    {
        const __nv_bfloat16* U = g_U[layer];
        #pragma unroll
        for (int j = 0; j < 16; j++) {
            int i = tid + j * STH;
            int r = i >> 3, c = i & 7;
            *(uint4*)&sU[r * LDSU + c * 8] = *(const uint4*)(U + (size_t)r * UNITS + n0 + c * 8);
        }
        if (hasZ) {
            const __nv_bfloat16* W = g_W[layer];
            #pragma unroll
            for (int j = 0; j < 16; j++) {
                int i = tid + j * STH;
                int r = i >> 3, c = i & 7;
                *(uint4*)&sW[r * LDSU + c * 8] = *(const uint4*)(W + (size_t)r * UNITS + n0 + c * 8);
            }
        }
        if (tid < BN) sBias[tid] = bias[n0 + tid];
    }
    __syncthreads();

    // epilogue mapping: thread -> row tid>>1, 32 cols at (tid&1)*32
    const int erow = tid >> 1;
    const int ecb  = (tid & 1) * 32;
    const int bRow = m0 + erow;
    const int itMax = hasZ ? SEQ : (SEQ - 1);
    unsigned tgt = barBase;

    for (int it = 0; it <= itMax; it++) {
        const bool doRec = (it < SEQ);
        const bool doZ   = (hasZ && it >= 1);

        if (it == 0) {
            // h_0 = tanh(Z_0 + b)
            size_t eidx = (size_t)bRow * UNITS + n0 + ecb;
            __nv_bfloat162 zb[16];
            #pragma unroll
            for (int q = 0; q < 4; q++)
                *(uint4*)&zb[q * 4] = *(const uint4*)(g_Z + eidx + q * 8);
            __nv_bfloat162 o[16];
            #pragma unroll
            for (int c = 0; c < 16; c++)
                o[c] = __floats2bfloat162_rn(tanhfast(__low2float(zb[c])  + sBias[ecb + 2*c]),
                                             tanhfast(__high2float(zb[c]) + sBias[ecb + 2*c + 1]));
            #pragma unroll
            for (int q = 0; q < 4; q++)
                *(uint4*)(g_H + eidx + q * 8) = *(uint4*)&o[q * 4];

            tgt += 8;
            __syncthreads();
            if (tid == 0) {
                arrive_release(&g_arr[mg]);
                while (ld_acquire(&g_arr[mg]) < tgt) { }
            }
            __syncthreads();
            continue;
        }

        // A = h_{it-1} slab (time-major, contiguous)
        const __nv_bfloat16* A = g_H + (size_t)(it - 1) * BATCH * UNITS + (size_t)m0 * UNITS;

        // prologue: A chunks 0,1 (3-buffer, R10-proven ordering)
        #pragma unroll
        for (int cidx = 0; cidx < 2; cidx++) {
            #pragma unroll
            for (int j = 0; j < 4; j++) {
                int i = tid + j * STH;
                int r = i >> 3, c = i & 7;
                cp16(aBase + cidx * ABUF + r * (LDSA * 2) + c * 16,
                     A + (size_t)r * UNITS + cidx * 64 + c * 8);
            }
            CP_COMMIT();
        }

        // own-Z prefetch (32 cols/thread)
        uint4 zr[4];
        if (doRec) {
            const uint4* zp = (const uint4*)(g_Z + ((size_t)it * BATCH + bRow) * UNITS + n0 + ecb);
            #pragma unroll
            for (int q = 0; q < 4; q++) zr[q] = zp[q];
        }

        wmma::fragment<wmma::accumulator, 16, 16, 16, float> accR[2][2], accZ[2][2];
        #pragma unroll
        for (int i = 0; i < 2; i++)
            #pragma unroll
            for (int j = 0; j < 2; j++) {
                if (doRec) wmma::fill_fragment(accR[i][j], 0.f);
                if (doZ)   wmma::fill_fragment(accZ[i][j], 0.f);
            }

        for (int kc = 0; kc < 8; kc++) {
            if (kc < 7) CP_WAIT1(); else CP_WAIT0();
            __syncthreads();
            if (kc + 2 < 8) {
                int nb = (kc + 2) % 3;
                #pragma unroll
                for (int j = 0; j < 4; j++) {
                    int i = tid + j * STH;
                    int r = i >> 3, c = i & 7;
                    cp16(aBase + nb * ABUF + r * (LDSA * 2) + c * 16,
                         A + (size_t)r * UNITS + (kc + 2) * 64 + c * 8);
                }
                CP_COMMIT();
            }
            const __nv_bfloat16* sA  = (const __nv_bfloat16*)(smraw + SM_A + (kc % 3) * ABUF);
            const __nv_bfloat16* sUw = sU + (kc * 64) * LDSU + wn * 32;
            const __nv_bfloat16* sWw = sW + (kc * 64) * LDSU + wn * 32;
            #pragma unroll
            for (int kk = 0; kk < 64; kk += 16) {
                wmma::fragment<wmma::matrix_a, 16, 16, 16, __nv_bfloat16, wmma::row_major> a0, a1;
                wmma::load_matrix_sync(a0, sA + (wm * 32) * LDSA + kk, LDSA);
                wmma::load_matrix_sync(a1, sA + (wm * 32 + 16) * LDSA + kk, LDSA);
                if (doRec) {
                    wmma::fragment<wmma::matrix_b, 16, 16, 16, __nv_bfloat16, wmma::row_major> b0, b1;
                    wmma::load_matrix_sync(b0, sUw + kk * LDSU, LDSU);
                    wmma::load_matrix_sync(b1, sUw + kk * LDSU + 16, LDSU);
                    wmma::mma_sync(accR[0][0], a0, b0, accR[0][0]);
                    wmma::mma_sync(accR[0][1], a0, b1, accR[0][1]);
                    wmma::mma_sync(accR[1][0], a1, b0, accR[1][0]);
                    wmma::mma_sync(accR[1][1], a1, b1, accR[1][1]);
                }
                if (doZ) {
                    wmma::fragment<wmma::matrix_b, 16, 16, 16, __nv_bfloat16, wmma::row_major> c0, c1;
                    wmma::load_matrix_sync(c0, sWw + kk * LDSU, LDSU);
                    wmma::load_matrix_sync(c1, sWw + kk * LDSU + 16, LDSU);
                    wmma::mma_sync(accZ[0][0], a0, c0, accZ[0][0]);
                    wmma::mma_sync(accZ[0][1], a0, c1, accZ[0][1]);
                    wmma::mma_sync(accZ[1][0], a1, c0, accZ[1][0]);
                    wmma::mma_sync(accZ[1][1], a1, c1, accZ[1][1]);
                }
            }
        }
        __syncthreads();   // MMA done; A buffers (sC alias) free

        if (doRec) {
            // h_t = tanh(R + Z + b) via coalescing smem stage
            #pragma unroll
            for (int i = 0; i < 2; i++)
                #pragma unroll
                for (int j = 0; j < 2; j++)
                    wmma::store_matrix_sync(&sC[(wm * 32 + i * 16) * LDSC + wn * 32 + j * 16],
                                            accR[i][j], LDSC, wmma::mem_row_major);
            __syncthreads();
            const float* s = &sC[erow * LDSC + ecb];
            __nv_bfloat162 zb[16];
            #pragma unroll
            for (int q = 0; q < 4; q++) *(uint4*)&zb[q * 4] = zr[q];
            __nv_bfloat162 o[16];
            size_t eidx = ((size_t)it * BATCH + bRow) * UNITS + n0 + ecb;
            #pragma unroll
            for (int c = 0; c < 16; c++)
                o[c] = __floats2bfloat162_rn(
                    tanhfast(s[2*c]     + __low2float(zb[c])  + sBias[ecb + 2*c]),
                    tanhfast(s[2*c + 1] + __high2float(zb[c]) + sBias[ecb + 2*c + 1]));
            #pragma unroll
            for (int q = 0; q < 4; q++)
                *(uint4*)(g_H + eidx + q * 8) = *(uint4*)&o[q * 4];
        }

        const bool needBar = doRec && (hasZ || it < SEQ - 1);
        if (needBar) {
            tgt += 8;
            __syncthreads();              // h stores issued + sC reads done
            if (tid == 0) arrive_release(&g_arr[mg]);   // early arrive; Z fills the gap
        }

        if (doZ) {
            // Z^{l+1}_{it-1} -> g_Z (block-local rows)
            #pragma unroll
            for (int i = 0; i < 2; i++)
                #pragma unroll
                for (int j = 0; j < 2; j++)
                    wmma::store_matrix_sync(&sC[(wm * 32 + i * 16) * LDSC + wn * 32 + j * 16],
                                            accZ[i][j], LDSC, wmma::mem_row_major);
            __syncthreads();
            const float* s = &sC[erow * LDSC + ecb];
            __nv_bfloat162 o[16];
            #pragma unroll
            for (int c = 0; c < 16; c++)
                o[c] = __floats2bfloat162_rn(s[2*c], s[2*c + 1]);
            __nv_bfloat16* dst = g_Z + ((size_t)(it - 1) * BATCH + bRow) * UNITS + n0 + ecb;
            #pragma unroll
            for (int q = 0; q < 4; q++)
                *(uint4*)(dst + q * 8) = *(uint4*)&o[q * 4];
        }

        if (needBar) {
            if (tid == 0) {
                while (ld_acquire(&g_arr[mg]) < tgt) { }
            }
            __syncthreads();
        } else if (it != itMax) {
            __syncthreads();
        }
    }
}

// ---------------- head ----------------
__global__ void head(const float* __restrict__ Wo, const float* __restrict__ bo,
                     float* __restrict__ out) {
    int gt = blockIdx.x * blockDim.x + threadIdx.x;
    int w = gt >> 5, lane = gt & 31;
    if (w >= BATCH) return;
    const __nv_bfloat16* h = g_H + ((size_t)(SEQ - 1) * BATCH + w) * UNITS;
    float s = 0.f;
    for (int k = lane; k < UNITS; k += 32)
        s += __bfloat162float(h[k]) * Wo[k];
    #pragma unroll
    for (int o = 16; o; o >>= 1) s += __shfl_xor_sync(0xffffffffu, s, o);
    if (lane == 0) out[w] = 1.f / (1.f + expf(-(s + bo[0])));
}

// ---------------- launch ----------------
extern "C" void kernel_launch(void* const* d_in, const int* in_sizes, int n_in,
                              void* d_out, int out_size) {
    const int*   tokens = (const int*)d_in[0];
    const float* emb    = (const float*)d_in[1];
    const float* Wm[4]  = {(const float*)d_in[2],  (const float*)d_in[5],
                           (const float*)d_in[8],  (const float*)d_in[11]};
    const float* Um[4]  = {(const float*)d_in[3],  (const float*)d_in[6],
                           (const float*)d_in[9],  (const float*)d_in[12]};
    const float* bm[4]  = {(const float*)d_in[4],  (const float*)d_in[7],
                           (const float*)d_in[10], (const float*)d_in[13]};
    const float* Wo = (const float*)d_in[14];
    const float* bo = (const float*)d_in[15];
    float* out = (float*)d_out;

    cudaFuncSetAttribute(gemm0,      cudaFuncAttributeMaxDynamicSharedMemorySize, BULK_SMEM);
    cudaFuncSetAttribute(scan_layer, cudaFuncAttributeMaxDynamicSharedMemorySize, SCAN_SMEM);

    void* barAddr = nullptr;
    cudaGetSymbolAddress(&barAddr, g_arr);
    cudaMemsetAsync(barAddr, 0, 16 * sizeof(unsigned int));

    embed_kernel<<<(int)(((size_t)BT * EMBP + 255) / 256), 256>>>(tokens, emb);

    dim3 pg(1024, 8);
    prep_all<<<pg, 256>>>(Wm[0], Wm[1], Wm[2], Wm[3], Um[0], Um[1], Um[2], Um[3]);

    dim3 gin(UNITS / GBN, BT / BM);     // (4, 1280)
    gemm0<<<gin, THREADS, BULK_SMEM>>>();

    for (int l = 0; l < 4; l++) {
        int hasZ = (l < 3) ? 1 : 0;
        scan_layer<<<NBLK, STH, SCAN_SMEM>>>(l, bm[l], hasZ, (unsigned)(l * SEQ * 8));
    }
    head<<<(BATCH * 32 + 255) / 256, 256>>>(Wo, bo, out);
}

// round 15
// speedup vs baseline: 1.1522x; 1.0166x over previous
#include <cuda_runtime.h>
#include <cuda_bf16.h>
#include <mma.h>
#include <math.h>
#include <cstdint>

using namespace nvcuda;

#define BATCH 2048
#define SEQ   80
#define UNITS 512
#define EMB   100
#define EMBP  128
#define BT    (BATCH*SEQ)
#define THREADS 512              // gemm0 / preps
#define STH     128              // scan threads (4 warps, 2x2 of 32x32 tiles)

// ---- scan tiling: BM=64, 2 CTAs/SM ----
#define BM 64
#define BN 64
#define NBLK 256                 // 32 m-groups x 8 n-tiles
#define LDSU 72
#define LDSA 72
#define LDSC 68
#define ABUF 9216                // 64*72*2
#define SM_U    0                // 512*72*2 = 73728
#define SM_A    73728            // 2 bufs: 73728, 82944 (sC f32 aliases here, 17408B)
#define SM_W    92160            // 2 bufs: 92160, 101376
#define SM_BIAS 110592
#define SCAN_SMEM 110848

// ---- layer-0 bulk tiling (unchanged) ----
#define GBM 128
#define GBN 128
#define LDBB 136
#define LDBA 72
#define LDBC 132
#define BULK_ABUF 18432
#define GM_B 0
#define GM_A 139264
#define BULK_SMEM 194560

// ---------------- persistent device scratch (TIME-MAJOR: [t][batch][.]) ----------------
__device__ __nv_bfloat16 g_X[(size_t)BT * EMBP];
__device__ __nv_bfloat16 g_Z[(size_t)BT * UNITS];
__device__ __nv_bfloat16 g_H[(size_t)BT * UNITS];
__device__ __nv_bfloat16 g_W1p[EMBP * UNITS];
__device__ __nv_bfloat16 g_W[3][UNITS * UNITS];     // g_W[l] = Wm[l+1]
__device__ __nv_bfloat16 g_U[4][UNITS * UNITS];
__device__ unsigned int  g_arr[32 * 16];            // 32 m-group counters, 64B stride

// ---------------- helpers ----------------
__device__ __forceinline__ uint32_t smem_u32(const void* p) {
    uint32_t a;
    asm("{ .reg .u64 t; cvta.to.shared.u64 t, %1; cvt.u32.u64 %0, t; }" : "=r"(a) : "l"(p));
    return a;
}
__device__ __forceinline__ void cp16(uint32_t dst, const void* src) {
    asm volatile("cp.async.cg.shared.global [%0], [%1], 16;" :: "r"(dst), "l"(src));
}
#define CP_COMMIT() asm volatile("cp.async.commit_group;" ::: "memory")
#define CP_WAIT1()  asm volatile("cp.async.wait_group 1;" ::: "memory")
#define CP_WAIT0()  asm volatile("cp.async.wait_group 0;" ::: "memory")

__device__ __forceinline__ void arrive_release(unsigned int* p) {
    asm volatile("red.release.gpu.global.add.u32 [%0], %1;" :: "l"(p), "r"(1u) : "memory");
}
__device__ __forceinline__ unsigned ld_acquire(const unsigned int* p) {
    unsigned v;
    asm volatile("ld.acquire.gpu.global.u32 %0, [%1];" : "=r"(v) : "l"(p) : "memory");
    return v;
}
__device__ __forceinline__ float tanhfast(float x) {
    float y;
    asm("tanh.approx.f32 %0, %1;" : "=f"(y) : "f"(x));
    return y;
}

// ---------------- embed + weight prep ----------------
__global__ void embed_kernel(const int* __restrict__ tokens, const float* __restrict__ emb) {
    size_t idx = (size_t)blockIdx.x * blockDim.x + threadIdx.x;
    if (idx >= (size_t)BT * EMBP) return;
    size_t row = idx >> 7;          // t*BATCH + b
    int col = (int)(idx & 127);
    int t = (int)(row >> 11);
    int b = (int)(row & 2047);
    int tok = tokens[(size_t)b * SEQ + t];
    float v = (col < EMB) ? emb[(size_t)tok * EMB + col] : 0.f;
    g_X[idx] = __float2bfloat16(v);
}

__global__ void prep_all(const float* __restrict__ W1, const float* __restrict__ W2,
                         const float* __restrict__ W3, const float* __restrict__ W4,
                         const float* __restrict__ U1, const float* __restrict__ U2,
                         const float* __restrict__ U3, const float* __restrict__ U4) {
    int y = blockIdx.y;
    int idx = blockIdx.x * blockDim.x + threadIdx.x;
    if (y == 0) {
        if (idx < EMBP * UNITS) {
            int k = idx >> 9, n = idx & 511;
            g_W1p[idx] = __float2bfloat16(k < EMB ? W1[k * UNITS + n] : 0.f);
        }
    } else if (y <= 3) {
        const float* s = (y == 1) ? W2 : (y == 2) ? W3 : W4;
        if (idx < UNITS * UNITS) g_W[y - 1][idx] = __float2bfloat16(s[idx]);
    } else {
        const float* s = (y == 4) ? U1 : (y == 5) ? U2 : (y == 6) ? U3 : U4;
        if (idx < UNITS * UNITS) g_U[y - 4][idx] = __float2bfloat16(s[idx]);
    }
}

// ---------------- layer-0 bulk GEMM: g_Z = X @ W1p (unchanged from R14) ----------------
__global__ __launch_bounds__(THREADS, 1) void gemm0() {
    extern __shared__ __align__(16) unsigned char smraw[];
    __nv_bfloat16* sB = (__nv_bfloat16*)(smraw + GM_B);
    float*         sC = (float*)(smraw + GM_B);

    const __nv_bfloat16* Ag = g_X;
    const __nv_bfloat16* Bg = g_W1p;
    const int K = EMBP, aStride = EMBP, KC = 2;

    const int n0 = blockIdx.x * GBN;
    const int m0 = blockIdx.y * GBM;
    const int tid = threadIdx.x;
    const int wid = tid >> 5;
    const int wm = wid & 3, wn = wid >> 2;

    const uint32_t sbase = smem_u32(smraw);
    const uint32_t aBase = sbase + GM_A;

    for (int i = tid; i < K * 16; i += THREADS) {
        int r = i >> 4, c = i & 15;
        cp16(sbase + GM_B + r * (LDBB * 2) + c * 16, Bg + (size_t)r * UNITS + n0 + c * 8);
    }
    {
        #pragma unroll
        for (int j = 0; j < 2; j++) {
            int i = tid + j * THREADS;
            int r = i >> 3, c = i & 7;
            cp16(aBase + r * (LDBA * 2) + c * 16, Ag + (size_t)(m0 + r) * aStride + c * 8);
        }
    }
    CP_COMMIT();

    wmma::fragment<wmma::accumulator, 16, 16, 16, float> acc[2][2];
    #pragma unroll
    for (int i = 0; i < 2; i++)
        #pragma unroll
        for (int j = 0; j < 2; j++) wmma::fill_fragment(acc[i][j], 0.f);

    int buf = 0;
    for (int kc = 0; kc < KC; kc++) {
        if (kc + 1 < KC) {
            int nb = buf + 1;
            #pragma unroll
            for (int j = 0; j < 2; j++) {
                int i = tid + j * THREADS;
                int r = i >> 3, c = i & 7;
                cp16(aBase + nb * BULK_ABUF + r * (LDBA * 2) + c * 16,
                     Ag + (size_t)(m0 + r) * aStride + (kc + 1) * 64 + c * 8);
            }
            CP_COMMIT();
            CP_WAIT1();
        } else {
            CP_WAIT0();
        }
        __syncthreads();

        const __nv_bfloat16* sA = (const __nv_bfloat16*)(smraw + GM_A + buf * BULK_ABUF);
        #pragma unroll
        for (int kk = 0; kk < 64; kk += 16) {
            wmma::fragment<wmma::matrix_a, 16, 16, 16, __nv_bfloat16, wmma::row_major> a0, a1;
            wmma::fragment<wmma::matrix_b, 16, 16, 16, __nv_bfloat16, wmma::row_major> b0, b1;
            wmma::load_matrix_sync(a0, sA + (wm * 32) * LDBA + kk, LDBA);
            wmma::load_matrix_sync(a1, sA + (wm * 32 + 16) * LDBA + kk, LDBA);
            wmma::load_matrix_sync(b0, sB + (kc * 64 + kk) * LDBB + wn * 32, LDBB);
            wmma::load_matrix_sync(b1, sB + (kc * 64 + kk) * LDBB + wn * 32 + 16, LDBB);
            wmma::mma_sync(acc[0][0], a0, b0, acc[0][0]);
            wmma::mma_sync(acc[0][1], a0, b1, acc[0][1]);
            wmma::mma_sync(acc[1][0], a1, b0, acc[1][0]);
            wmma::mma_sync(acc[1][1], a1, b1, acc[1][1]);
        }
        buf++;
    }
    __syncthreads();

    #pragma unroll
    for (int i = 0; i < 2; i++)
        #pragma unroll
        for (int j = 0; j < 2; j++)
            wmma::store_matrix_sync(&sC[(wm * 32 + i * 16) * LDBC + wn * 32 + j * 16],
                                    acc[i][j], LDBC, wmma::mem_row_major);
    __syncthreads();

    {
        const int erow = tid >> 2;
        const int ecb  = (tid & 3) * 32;
        const float* s = &sC[erow * LDBC + ecb];
        __nv_bfloat162 p[16];
        #pragma unroll
        for (int q = 0; q < 16; q++) p[q] = __floats2bfloat162_rn(s[2*q], s[2*q+1]);
        __nv_bfloat16* dst = g_Z + (size_t)(m0 + erow) * UNITS + n0 + ecb;
        #pragma unroll
        for (int q = 0; q < 4; q++)
            *(uint4*)(dst + q * 8) = *(uint4*)&p[q * 4];
    }
}

// ---------------- persistent scan: BM=64, 2 CTAs/SM, U resident, A+W streamed ----------------
__global__ __launch_bounds__(STH, 2)
void scan_layer(int layer, const float* __restrict__ bias, int hasZ, unsigned barBase) {
    extern __shared__ __align__(16) unsigned char smraw[];
    __nv_bfloat16* sU = (__nv_bfloat16*)(smraw + SM_U);
    float*         sC = (float*)(smraw + SM_A);       // aliases A buffers in epilogue
    float*         sBias = (float*)(smraw + SM_BIAS);
    const uint32_t sbase = smem_u32(smraw);
    const uint32_t aBase = sbase + SM_A;
    const uint32_t wBase = sbase + SM_W;

    const int tid = threadIdx.x;
    const int wid = tid >> 5;
    const int bid = blockIdx.x;
    const int n0 = (bid & 7) * BN;
    const int mg = bid >> 3;                          // 0..31
    const int m0 = mg * BM;
    const int wm = wid & 1;                           // 2 m-slices of 32
    const int wn = wid >> 1;                          // 2 n-slices of 32

    unsigned int* grpCtr = &g_arr[mg * 16];
    const __nv_bfloat16* Wg = g_W[hasZ ? layer : 0];  // unused when !hasZ

    // stage U[:, n0:n0+64] once per layer
    {
        const __nv_bfloat16* U = g_U[layer];
        #pragma unroll
        for (int j = 0; j < 32; j++) {
            int i = tid + j * STH;
            int r = i >> 3, c = i & 7;
            *(uint4*)&sU[r * LDSU + c * 8] = *(const uint4*)(U + (size_t)r * UNITS + n0 + c * 8);
        }
        if (tid < BN) sBias[tid] = bias[n0 + tid];
    }
    __syncthreads();

    // epilogue mapping: thread -> row tid>>1, 32 cols at (tid&1)*32
    const int erow = tid >> 1;
    const int ecb  = (tid & 1) * 32;
    const int bRow = m0 + erow;
    const int itMax = hasZ ? SEQ : (SEQ - 1);
    unsigned tgt = barBase;

    for (int it = 0; it <= itMax; it++) {
        const bool doRec = (it < SEQ);
        const bool doZ   = (hasZ && it >= 1);

        if (it == 0) {
            // h_0 = tanh(Z_0 + b)
            size_t eidx = (size_t)bRow * UNITS + n0 + ecb;
            __nv_bfloat162 zb[16];
            #pragma unroll
            for (int q = 0; q < 4; q++)
                *(uint4*)&zb[q * 4] = *(const uint4*)(g_Z + eidx + q * 8);
            __nv_bfloat162 o[16];
            #pragma unroll
            for (int c = 0; c < 16; c++)
                o[c] = __floats2bfloat162_rn(tanhfast(__low2float(zb[c])  + sBias[ecb + 2*c]),
                                             tanhfast(__high2float(zb[c]) + sBias[ecb + 2*c + 1]));
            #pragma unroll
            for (int q = 0; q < 4; q++)
                *(uint4*)(g_H + eidx + q * 8) = *(uint4*)&o[q * 4];

            tgt += 8;
            __syncthreads();
            if (tid == 0) {
                arrive_release(grpCtr);
                while (ld_acquire(grpCtr) < tgt) { }
            }
            __syncthreads();
            continue;
        }

        // A = h_{it-1} slab rows m0..m0+63
        const __nv_bfloat16* A = g_H + (size_t)(it - 1) * BATCH * UNITS + (size_t)m0 * UNITS;

        // prologue: chunk 0 (A + optional W), buf 0
        {
            #pragma unroll
            for (int j = 0; j < 4; j++) {
                int i = tid + j * STH;
                int r = i >> 3, c = i & 7;
                cp16(aBase + r * (LDSA * 2) + c * 16, A + (size_t)r * UNITS + c * 8);
            }
            if (hasZ) {
                #pragma unroll
                for (int j = 0; j < 4; j++) {
                    int i = tid + j * STH;
                    int r = i >> 3, c = i & 7;
                    cp16(wBase + r * (LDSU * 2) + c * 16, Wg + (size_t)r * UNITS + n0 + c * 8);
                }
            }
            CP_COMMIT();
        }

        // own-Z prefetch (32 cols/thread)
        uint4 zr[4];
        if (doRec) {
            const uint4* zp = (const uint4*)(g_Z + ((size_t)it * BATCH + bRow) * UNITS + n0 + ecb);
            #pragma unroll
            for (int q = 0; q < 4; q++) zr[q] = zp[q];
        }

        wmma::fragment<wmma::accumulator, 16, 16, 16, float> accR[2][2], accZ[2][2];
        #pragma unroll
        for (int i = 0; i < 2; i++)
            #pragma unroll
            for (int j = 0; j < 2; j++) {
                if (doRec) wmma::fill_fragment(accR[i][j], 0.f);
                if (doZ)   wmma::fill_fragment(accZ[i][j], 0.f);
            }

        int buf = 0;
        for (int kc = 0; kc < 8; kc++) {
            if (kc + 1 < 8) {
                // prefetch chunk kc+1 into buf^1 (free since end of chunk kc-1)
                int nb = buf ^ 1;
                #pragma unroll
                for (int j = 0; j < 4; j++) {
                    int i = tid + j * STH;
                    int r = i >> 3, c = i & 7;
                    cp16(aBase + nb * ABUF + r * (LDSA * 2) + c * 16,
                         A + (size_t)r * UNITS + (kc + 1) * 64 + c * 8);
                }
                if (hasZ) {
                    #pragma unroll
                    for (int j = 0; j < 4; j++) {
                        int i = tid + j * STH;
                        int r = i >> 3, c = i & 7;
                        cp16(wBase + nb * ABUF + r * (LDSU * 2) + c * 16,
                             Wg + (size_t)((kc + 1) * 64 + r) * UNITS + n0 + c * 8);
                    }
                }
                CP_COMMIT();
                CP_WAIT1();        // chunk kc complete (this thread)
            } else {
                CP_WAIT0();
            }
            __syncthreads();        // chunk kc landed block-wide

            const __nv_bfloat16* sA  = (const __nv_bfloat16*)(smraw + SM_A + buf * ABUF);
            const __nv_bfloat16* sWc = (const __nv_bfloat16*)(smraw + SM_W + buf * ABUF);
            const __nv_bfloat16* sUw = sU + (kc * 64) * LDSU + wn * 32;
            #pragma unroll
            for (int kk = 0; kk < 64; kk += 16) {
                wmma::fragment<wmma::matrix_a, 16, 16, 16, __nv_bfloat16, wmma::row_major> a0, a1;
                wmma::load_matrix_sync(a0, sA + (wm * 32) * LDSA + kk, LDSA);
                wmma::load_matrix_sync(a1, sA + (wm * 32 + 16) * LDSA + kk, LDSA);
                if (doRec) {
                    wmma::fragment<wmma::matrix_b, 16, 16, 16, __nv_bfloat16, wmma::row_major> b0, b1;
                    wmma::load_matrix_sync(b0, sUw + kk * LDSU, LDSU);
                    wmma::load_matrix_sync(b1, sUw + kk * LDSU + 16, LDSU);
                    wmma::mma_sync(accR[0][0], a0, b0, accR[0][0]);
                    wmma::mma_sync(accR[0][1], a0, b1, accR[0][1]);
                    wmma::mma_sync(accR[1][0], a1, b0, accR[1][0]);
                    wmma::mma_sync(accR[1][1], a1, b1, accR[1][1]);
                }
                if (doZ) {
                    wmma::fragment<wmma::matrix_b, 16, 16, 16, __nv_bfloat16, wmma::row_major> c0, c1;
                    wmma::load_matrix_sync(c0, sWc + kk * LDSU + wn * 32, LDSU);
                    wmma::load_matrix_sync(c1, sWc + kk * LDSU + wn * 32 + 16, LDSU);
                    wmma::mma_sync(accZ[0][0], a0, c0, accZ[0][0]);
                    wmma::mma_sync(accZ[0][1], a0, c1, accZ[0][1]);
                    wmma::mma_sync(accZ[1][0], a1, c0, accZ[1][0]);
                    wmma::mma_sync(accZ[1][1], a1, c1, accZ[1][1]);
                }
            }
            __syncthreads();        // reads done; buf free for next prefetch
            buf ^= 1;
        }
        // A/W buffers free (sC alias safe)

        if (doRec) {
            // h_t = tanh(R + Z + b) via coalescing smem stage
            #pragma unroll
            for (int i = 0; i < 2; i++)
                #pragma unroll
                for (int j = 0; j < 2; j++)
                    wmma::store_matrix_sync(&sC[(wm * 32 + i * 16) * LDSC + wn * 32 + j * 16],
                                            accR[i][j], LDSC, wmma::mem_row_major);
            __syncthreads();
            const float* s = &sC[erow * LDSC + ecb];
            __nv_bfloat162 zb[16];
            #pragma unroll
            for (int q = 0; q < 4; q++) *(uint4*)&zb[q * 4] = zr[q];
            __nv_bfloat162 o[16];
            size_t eidx = ((size_t)it * BATCH + bRow) * UNITS + n0 + ecb;
            #pragma unroll
            for (int c = 0; c < 16; c++)
                o[c] = __floats2bfloat162_rn(
                    tanhfast(s[2*c]     + __low2float(zb[c])  + sBias[ecb + 2*c]),
                    tanhfast(s[2*c + 1] + __high2float(zb[c]) + sBias[ecb + 2*c + 1]));
            #pragma unroll
            for (int q = 0; q < 4; q++)
                *(uint4*)(g_H + eidx + q * 8) = *(uint4*)&o[q * 4];
        }

        const bool needBar = doRec && (hasZ || it < SEQ - 1);
        if (needBar) {
            tgt += 8;
            __syncthreads();              // h stores issued + sC reads done
            if (tid == 0) arrive_release(grpCtr);   // early arrive; Z fills the gap
        }

        if (doZ) {
            // Z^{l+1}_{it-1} -> g_Z
            #pragma unroll
            for (int i = 0; i < 2; i++)
                #pragma unroll
                for (int j = 0; j < 2; j++)
                    wmma::store_matrix_sync(&sC[(wm * 32 + i * 16) * LDSC + wn * 32 + j * 16],
                                            accZ[i][j], LDSC, wmma::mem_row_major);
            __syncthreads();
            const float* s = &sC[erow * LDSC + ecb];
            __nv_bfloat162 o[16];
            #pragma unroll
            for (int c = 0; c < 16; c++)
                o[c] = __floats2bfloat162_rn(s[2*c], s[2*c + 1]);
            __nv_bfloat16* dst = g_Z + ((size_t)(it - 1) * BATCH + bRow) * UNITS + n0 + ecb;
            #pragma unroll
            for (int q = 0; q < 4; q++)
                *(uint4*)(dst + q * 8) = *(uint4*)&o[q * 4];
        }

        if (needBar) {
            if (tid == 0) {
                while (ld_acquire(grpCtr) < tgt) { }
            }
            __syncthreads();
        } else if (it != itMax) {
            __syncthreads();
        }
    }
}

// ---------------- head ----------------
__global__ void head(const float* __restrict__ Wo, const float* __restrict__ bo,
                     float* __restrict__ out) {
    int gt = blockIdx.x * blockDim.x + threadIdx.x;
    int w = gt >> 5, lane = gt & 31;
    if (w >= BATCH) return;
    const __nv_bfloat16* h = g_H + ((size_t)(SEQ - 1) * BATCH + w) * UNITS;
    float s = 0.f;
    for (int k = lane; k < UNITS; k += 32)
        s += __bfloat162float(h[k]) * Wo[k];
    #pragma unroll
    for (int o = 16; o; o >>= 1) s += __shfl_xor_sync(0xffffffffu, s, o);
    if (lane == 0) out[w] = 1.f / (1.f + expf(-(s + bo[0])));
}

// ---------------- launch ----------------
extern "C" void kernel_launch(void* const* d_in, const int* in_sizes, int n_in,
                              void* d_out, int out_size) {
    const int*   tokens = (const int*)d_in[0];
    const float* emb    = (const float*)d_in[1];
    const float* Wm[4]  = {(const float*)d_in[2],  (const float*)d_in[5],
                           (const float*)d_in[8],  (const float*)d_in[11]};
    const float* Um[4]  = {(const float*)d_in[3],  (const float*)d_in[6],
                           (const float*)d_in[9],  (const float*)d_in[12]};
    const float* bm[4]  = {(const float*)d_in[4],  (const float*)d_in[7],
                           (const float*)d_in[10], (const float*)d_in[13]};
    const float* Wo = (const float*)d_in[14];
    const float* bo = (const float*)d_in[15];
    float* out = (float*)d_out;

    cudaFuncSetAttribute(gemm0,      cudaFuncAttributeMaxDynamicSharedMemorySize, BULK_SMEM);
    cudaFuncSetAttribute(scan_layer, cudaFuncAttributeMaxDynamicSharedMemorySize, SCAN_SMEM);

    void* barAddr = nullptr;
    cudaGetSymbolAddress(&barAddr, g_arr);
    cudaMemsetAsync(barAddr, 0, 32 * 16 * sizeof(unsigned int));

    embed_kernel<<<(int)(((size_t)BT * EMBP + 255) / 256), 256>>>(tokens, emb);

    dim3 pg(1024, 8);
    prep_all<<<pg, 256>>>(Wm[0], Wm[1], Wm[2], Wm[3], Um[0], Um[1], Um[2], Um[3]);

    dim3 gin(UNITS / GBN, BT / GBM);     // (4, 1280)
    gemm0<<<gin, THREADS, BULK_SMEM>>>();

    for (int l = 0; l < 4; l++) {
        int hasZ = (l < 3) ? 1 : 0;
        scan_layer<<<NBLK, STH, SCAN_SMEM>>>(l, bm[l], hasZ, (unsigned)(l * SEQ * 8));
    }
    head<<<(BATCH * 32 + 255) / 256, 256>>>(Wo, bo, out);
}

// round 16
// speedup vs baseline: 1.2750x; 1.1066x over previous
#include <cuda_runtime.h>
#include <cuda_bf16.h>
#include <mma.h>
#include <math.h>
#include <cstdint>

using namespace nvcuda;

#define BATCH 2048
#define SEQ   80
#define UNITS 512
#define EMB   100
#define EMBP  128
#define BT    (BATCH*SEQ)
#define THREADS 512              // gemm0 / preps
#define STH     128              // scan threads (4 warps, 2x2 of 64x32 warp tiles)

// ---- wavefront scan tiling: BM=128, BN=64, 2 CTAs/SM, 256 blocks = 2 layers ----
#define BM 128
#define BN 64
#define LDSU 72                  // U / W smem stride
#define LDSA 40                  // A chunk stride (32+8)
#define LDSC 68
#define ABUF 10240               // 128*40*2
#define WBUF 4608                // 32*72*2
#define SM_U    0                // 512*72*2 = 73728
#define SM_A    73728            // 2 bufs = 20480 (sC f32 64x68x4=17408 aliases)
#define SM_W    94208            // 2 bufs = 9216
#define SM_BIAS 103424           // 256
#define SCAN_SMEM 103680

// ---- layer-0 bulk tiling ----
#define GBM 128
#define GBN 128
#define LDBB 136
#define LDBA 72
#define LDBC 132
#define BULK_ABUF 18432
#define GM_B 0
#define GM_A 139264
#define BULK_SMEM 194560

// ---------------- persistent device scratch (TIME-MAJOR slabs) ----------------
__device__ __nv_bfloat16 g_X[(size_t)BT * EMBP];
__device__ __nv_bfloat16 g_Z[(size_t)BT * UNITS];    // gemm0 out / pair1 lo out
__device__ __nv_bfloat16 g_Zb[(size_t)BT * UNITS];   // pair0 lo out = pair0 hi in
__device__ __nv_bfloat16 g_Zc[(size_t)BT * UNITS];   // pair0 hi out = pair1 lo in
__device__ __nv_bfloat16 g_Ha[(size_t)BT * UNITS];   // lo-layer h
__device__ __nv_bfloat16 g_Hb[(size_t)BT * UNITS];   // hi-layer h (head reads last slab)
__device__ __nv_bfloat16 g_W1p[EMBP * UNITS];
__device__ __nv_bfloat16 g_W[3][UNITS * UNITS];      // g_W[l] = Wm[l+1]
__device__ __nv_bfloat16 g_U[4][UNITS * UNITS];
__device__ unsigned int  g_arr[4 * 16 * 16];         // [layer][mg] counters, 64B stride

// ---------------- helpers ----------------
__device__ __forceinline__ uint32_t smem_u32(const void* p) {
    uint32_t a;
    asm("{ .reg .u64 t; cvta.to.shared.u64 t, %1; cvt.u32.u64 %0, t; }" : "=r"(a) : "l"(p));
    return a;
}
__device__ __forceinline__ void cp16(uint32_t dst, const void* src) {
    asm volatile("cp.async.cg.shared.global [%0], [%1], 16;" :: "r"(dst), "l"(src));
}
#define CP_COMMIT() asm volatile("cp.async.commit_group;" ::: "memory")
#define CP_WAIT1()  asm volatile("cp.async.wait_group 1;" ::: "memory")
#define CP_WAIT0()  asm volatile("cp.async.wait_group 0;" ::: "memory")

__device__ __forceinline__ void arrive_release(unsigned int* p) {
    asm volatile("red.release.gpu.global.add.u32 [%0], %1;" :: "l"(p), "r"(1u) : "memory");
}
__device__ __forceinline__ unsigned ld_acquire(const unsigned int* p) {
    unsigned v;
    asm volatile("ld.acquire.gpu.global.u32 %0, [%1];" : "=r"(v) : "l"(p) : "memory");
    return v;
}
__device__ __forceinline__ float tanhfast(float x) {
    float y;
    asm("tanh.approx.f32 %0, %1;" : "=f"(y) : "f"(x));
    return y;
}

// ---------------- embed + weight prep ----------------
__global__ void embed_kernel(const int* __restrict__ tokens, const float* __restrict__ emb) {
    size_t idx = (size_t)blockIdx.x * blockDim.x + threadIdx.x;
    if (idx >= (size_t)BT * EMBP) return;
    size_t row = idx >> 7;          // t*BATCH + b
    int col = (int)(idx & 127);
    int t = (int)(row >> 11);
    int b = (int)(row & 2047);
    int tok = tokens[(size_t)b * SEQ + t];
    float v = (col < EMB) ? emb[(size_t)tok * EMB + col] : 0.f;
    g_X[idx] = __float2bfloat16(v);
}

__global__ void prep_all(const float* __restrict__ W1, const float* __restrict__ W2,
                         const float* __restrict__ W3, const float* __restrict__ W4,
                         const float* __restrict__ U1, const float* __restrict__ U2,
                         const float* __restrict__ U3, const float* __restrict__ U4) {
    int y = blockIdx.y;
    int idx = blockIdx.x * blockDim.x + threadIdx.x;
    if (y == 0) {
        if (idx < EMBP * UNITS) {
            int k = idx >> 9, n = idx & 511;
            g_W1p[idx] = __float2bfloat16(k < EMB ? W1[k * UNITS + n] : 0.f);
        }
    } else if (y <= 3) {
        const float* s = (y == 1) ? W2 : (y == 2) ? W3 : W4;
        if (idx < UNITS * UNITS) g_W[y - 1][idx] = __float2bfloat16(s[idx]);
    } else {
        const float* s = (y == 4) ? U1 : (y == 5) ? U2 : (y == 6) ? U3 : U4;
        if (idx < UNITS * UNITS) g_U[y - 4][idx] = __float2bfloat16(s[idx]);
    }
}

// ---------------- layer-0 bulk GEMM: g_Z = X @ W1p ----------------
__global__ __launch_bounds__(THREADS, 1) void gemm0() {
    extern __shared__ __align__(16) unsigned char smraw[];
    __nv_bfloat16* sB = (__nv_bfloat16*)(smraw + GM_B);
    float*         sC = (float*)(smraw + GM_B);

    const __nv_bfloat16* Ag = g_X;
    const __nv_bfloat16* Bg = g_W1p;
    const int K = EMBP, aStride = EMBP, KC = 2;

    const int n0 = blockIdx.x * GBN;
    const int m0 = blockIdx.y * GBM;
    const int tid = threadIdx.x;
    const int wid = tid >> 5;
    const int wm = wid & 3, wn = wid >> 2;

    const uint32_t sbase = smem_u32(smraw);
    const uint32_t aBase = sbase + GM_A;

    for (int i = tid; i < K * 16; i += THREADS) {
        int r = i >> 4, c = i & 15;
        cp16(sbase + GM_B + r * (LDBB * 2) + c * 16, Bg + (size_t)r * UNITS + n0 + c * 8);
    }
    {
        #pragma unroll
        for (int j = 0; j < 2; j++) {
            int i = tid + j * THREADS;
            int r = i >> 3, c = i & 7;
            cp16(aBase + r * (LDBA * 2) + c * 16, Ag + (size_t)(m0 + r) * aStride + c * 8);
        }
    }
    CP_COMMIT();

    wmma::fragment<wmma::accumulator, 16, 16, 16, float> acc[2][2];
    #pragma unroll
    for (int i = 0; i < 2; i++)
        #pragma unroll
        for (int j = 0; j < 2; j++) wmma::fill_fragment(acc[i][j], 0.f);

    int buf = 0;
    for (int kc = 0; kc < KC; kc++) {
        if (kc + 1 < KC) {
            int nb = buf + 1;
            #pragma unroll
            for (int j = 0; j < 2; j++) {
                int i = tid + j * THREADS;
                int r = i >> 3, c = i & 7;
                cp16(aBase + nb * BULK_ABUF + r * (LDBA * 2) + c * 16,
                     Ag + (size_t)(m0 + r) * aStride + (kc + 1) * 64 + c * 8);
            }
            CP_COMMIT();
            CP_WAIT1();
        } else {
            CP_WAIT0();
        }
        __syncthreads();

        const __nv_bfloat16* sA = (const __nv_bfloat16*)(smraw + GM_A + buf * BULK_ABUF);
        #pragma unroll
        for (int kk = 0; kk < 64; kk += 16) {
            wmma::fragment<wmma::matrix_a, 16, 16, 16, __nv_bfloat16, wmma::row_major> a0, a1;
            wmma::fragment<wmma::matrix_b, 16, 16, 16, __nv_bfloat16, wmma::row_major> b0, b1;
            wmma::load_matrix_sync(a0, sA + (wm * 32) * LDBA + kk, LDBA);
            wmma::load_matrix_sync(a1, sA + (wm * 32 + 16) * LDBA + kk, LDBA);
            wmma::load_matrix_sync(b0, sB + (kc * 64 + kk) * LDBB + wn * 32, LDBB);
            wmma::load_matrix_sync(b1, sB + (kc * 64 + kk) * LDBB + wn * 32 + 16, LDBB);
            wmma::mma_sync(acc[0][0], a0, b0, acc[0][0]);
            wmma::mma_sync(acc[0][1], a0, b1, acc[0][1]);
            wmma::mma_sync(acc[1][0], a1, b0, acc[1][0]);
            wmma::mma_sync(acc[1][1], a1, b1, acc[1][1]);
        }
        buf++;
    }
    __syncthreads();

    #pragma unroll
    for (int i = 0; i < 2; i++)
        #pragma unroll
        for (int j = 0; j < 2; j++)
            wmma::store_matrix_sync(&sC[(wm * 32 + i * 16) * LDBC + wn * 32 + j * 16],
                                    acc[i][j], LDBC, wmma::mem_row_major);
    __syncthreads();

    {
        const int erow = tid >> 2;
        const int ecb  = (tid & 3) * 32;
        const float* s = &sC[erow * LDBC + ecb];
        __nv_bfloat162 p[16];
        #pragma unroll
        for (int q = 0; q < 16; q++) p[q] = __floats2bfloat162_rn(s[2*q], s[2*q+1]);
        __nv_bfloat16* dst = g_Z + (size_t)(m0 + erow) * UNITS + n0 + ecb;
        #pragma unroll
        for (int q = 0; q < 4; q++)
            *(uint4*)(dst + q * 8) = *(uint4*)&p[q * 4];
    }
}

// ---------------- wavefront pair scan: layers (layerLo, layerLo+1) concurrent ----------------
__global__ __launch_bounds__(STH, 2)
void scan_pair(int layerLo,
               const float* __restrict__ biasL, const float* __restrict__ biasH,
               __nv_bfloat16* zA, __nv_bfloat16* zB, __nv_bfloat16* zC,
               int hiHasZ) {
    extern __shared__ __align__(16) unsigned char smraw[];
    __nv_bfloat16* sU = (__nv_bfloat16*)(smraw + SM_U);
    float*         sC = (float*)(smraw + SM_A);     // 64x68 f32, aliases A bufs
    float*         sBias = (float*)(smraw + SM_BIAS);
    const uint32_t sbase = smem_u32(smraw);
    const uint32_t aBase = sbase + SM_A;
    const uint32_t wBase = sbase + SM_W;

    const int tid = threadIdx.x;
    const int wid = tid >> 5;
    const int bid = blockIdx.x;
    const int isHi = (bid >= 128) ? 1 : 0;
    const int lbid = bid & 127;
    const int nb = lbid & 7;
    const int mg = lbid >> 3;
    const int n0 = nb * BN;
    const int m0 = mg * BM;
    const int wm = wid & 1;          // 2 m-halves of 64
    const int wn = wid >> 1;         // 2 n-halves of 32

    const int layer = layerLo + isHi;
    const int hasZ  = isHi ? hiHasZ : 1;
    const __nv_bfloat16* Zin  = isHi ? zB : zA;
    __nv_bfloat16*       Zout = isHi ? zC : zB;
    __nv_bfloat16*       Hbuf = isHi ? g_Hb : g_Ha;
    const float*         bias = isHi ? biasH : biasL;
    const __nv_bfloat16* Wg   = hasZ ? g_W[layer] : g_W[0];

    unsigned int* ctrOwn = &g_arr[((layer) * 16 + mg) * 16];
    unsigned int* ctrLo  = &g_arr[((layerLo) * 16 + mg) * 16];

    // stage U[:, n0:n0+64] resident
    {
        const __nv_bfloat16* U = g_U[layer];
        #pragma unroll
        for (int j = 0; j < 32; j++) {
            int i = tid + j * STH;
            int r = i >> 3, c = i & 7;
            *(uint4*)&sU[r * LDSU + c * 8] = *(const uint4*)(U + (size_t)r * UNITS + n0 + c * 8);
        }
        if (tid < BN) sBias[tid] = bias[n0 + tid];
    }
    __syncthreads();
    // hi: wait for lo to publish Z_0 (lo iterations 0 and 1 done)
    if (isHi) {
        if (tid == 0) { while (ld_acquire(ctrLo) < 16u) { } }
        __syncthreads();
    }

    const int itMax = hasZ ? SEQ : (SEQ - 1);

    for (int it = 0; it <= itMax; it++) {
        const bool doRec = (it < SEQ);
        const bool doZ   = (hasZ && it >= 1);

        if (it == 0) {
            // h_0 = tanh(Z_0 + b): thread -> row tid, all 64 cols
            size_t eidx = (size_t)(m0 + tid) * UNITS + n0;
            __nv_bfloat162 zb[32];
            #pragma unroll
            for (int q = 0; q < 8; q++)
                *(uint4*)&zb[q * 4] = *(const uint4*)(Zin + eidx + q * 8);
            __nv_bfloat162 o[32];
            #pragma unroll
            for (int c = 0; c < 32; c++)
                o[c] = __floats2bfloat162_rn(tanhfast(__low2float(zb[c])  + sBias[2*c]),
                                             tanhfast(__high2float(zb[c]) + sBias[2*c + 1]));
            #pragma unroll
            for (int q = 0; q < 8; q++)
                *(uint4*)(Hbuf + eidx + q * 8) = *(uint4*)&o[q * 4];
        } else {
            // A = own h_{it-1} rows m0..m0+127
            const __nv_bfloat16* A = Hbuf + (size_t)(it - 1) * BATCH * UNITS + (size_t)m0 * UNITS;

            // prologue: chunk 0 -> buf 0
            {
                #pragma unroll
                for (int j = 0; j < 4; j++) {
                    int i = tid + j * STH;
                    int r = i >> 2, c = i & 3;
                    cp16(aBase + r * (LDSA * 2) + c * 16, A + (size_t)r * UNITS + c * 8);
                }
                if (doZ) {
                    #pragma unroll
                    for (int j = 0; j < 2; j++) {
                        int i = tid + j * STH;
                        int r = i >> 3, c = i & 7;
                        cp16(wBase + r * (LDSU * 2) + c * 16, Wg + (size_t)r * UNITS + n0 + c * 8);
                    }
                }
                CP_COMMIT();
            }

            wmma::fragment<wmma::accumulator, 16, 16, 16, float> accR[4][2], accZ[4][2];
            #pragma unroll
            for (int i = 0; i < 4; i++)
                #pragma unroll
                for (int j = 0; j < 2; j++) {
                    if (doRec) wmma::fill_fragment(accR[i][j], 0.f);
                    if (doZ)   wmma::fill_fragment(accZ[i][j], 0.f);
                }

            int buf = 0;
            for (int kc = 0; kc < 16; kc++) {
                if (kc + 1 < 16) {
                    int nbf = buf ^ 1;          // safe: its reads ended before prior sync
                    #pragma unroll
                    for (int j = 0; j < 4; j++) {
                        int i = tid + j * STH;
                        int r = i >> 2, c = i & 3;
                        cp16(aBase + nbf * ABUF + r * (LDSA * 2) + c * 16,
                             A + (size_t)r * UNITS + (kc + 1) * 32 + c * 8);
                    }
                    if (doZ) {
                        #pragma unroll
                        for (int j = 0; j < 2; j++) {
                            int i = tid + j * STH;
                            int r = i >> 3, c = i & 7;
                            cp16(wBase + nbf * WBUF + r * (LDSU * 2) + c * 16,
                                 Wg + (size_t)((kc + 1) * 32 + r) * UNITS + n0 + c * 8);
                        }
                    }
                    CP_COMMIT();
                    CP_WAIT1();
                } else {
                    CP_WAIT0();
                }
                __syncthreads();    // chunk kc landed block-wide

                const __nv_bfloat16* sA  = (const __nv_bfloat16*)(smraw + SM_A + buf * ABUF);
                const __nv_bfloat16* sWc = (const __nv_bfloat16*)(smraw + SM_W + buf * WBUF);
                #pragma unroll
                for (int kk = 0; kk < 32; kk += 16) {
                    wmma::fragment<wmma::matrix_a, 16, 16, 16, __nv_bfloat16, wmma::row_major> a[4];
                    #pragma unroll
                    for (int i = 0; i < 4; i++)
                        wmma::load_matrix_sync(a[i], sA + (wm * 64 + i * 16) * LDSA + kk, LDSA);
                    if (doRec) {
                        wmma::fragment<wmma::matrix_b, 16, 16, 16, __nv_bfloat16, wmma::row_major> b0, b1;
                        wmma::load_matrix_sync(b0, sU + (kc * 32 + kk) * LDSU + wn * 32, LDSU);
                        wmma::load_matrix_sync(b1, sU + (kc * 32 + kk) * LDSU + wn * 32 + 16, LDSU);
                        #pragma unroll
                        for (int i = 0; i < 4; i++) {
                            wmma::mma_sync(accR[i][0], a[i], b0, accR[i][0]);
                            wmma::mma_sync(accR[i][1], a[i], b1, accR[i][1]);
                        }
                    }
                    if (doZ) {
                        wmma::fragment<wmma::matrix_b, 16, 16, 16, __nv_bfloat16, wmma::row_major> c0, c1;
                        wmma::load_matrix_sync(c0, sWc + kk * LDSU + wn * 32, LDSU);
                        wmma::load_matrix_sync(c1, sWc + kk * LDSU + wn * 32 + 16, LDSU);
                        #pragma unroll
                        for (int i = 0; i < 4; i++) {
                            wmma::mma_sync(accZ[i][0], a[i], c0, accZ[i][0]);
                            wmma::mma_sync(accZ[i][1], a[i], c1, accZ[i][1]);
                        }
                    }
                }
                __syncthreads();    // reads done; buf free for next prefetch
                buf ^= 1;
            }

            // ---- R epilogue: h_it = tanh(R + Z + b), two 64-row half passes ----
            if (doRec) {
                #pragma unroll
                for (int p = 0; p < 2; p++) {
                    if (wm == p) {
                        #pragma unroll
                        for (int i = 0; i < 4; i++)
                            #pragma unroll
                            for (int j = 0; j < 2; j++)
                                wmma::store_matrix_sync(&sC[(i * 16) * LDSC + wn * 32 + j * 16],
                                                        accR[i][j], LDSC, wmma::mem_row_major);
                    }
                    __syncthreads();
                    {
                        int r = tid >> 1;
                        int ecb = (tid & 1) * 32;
                        int grow = m0 + p * 64 + r;
                        size_t eidx = ((size_t)it * BATCH + grow) * UNITS + n0 + ecb;
                        __nv_bfloat162 zb[16];
                        #pragma unroll
                        for (int q = 0; q < 4; q++)
                            *(uint4*)&zb[q * 4] = *(const uint4*)(Zin + eidx + q * 8);
                        const float* s = &sC[r * LDSC + ecb];
                        __nv_bfloat162 o[16];
                        #pragma unroll
                        for (int c = 0; c < 16; c++)
                            o[c] = __floats2bfloat162_rn(
                                tanhfast(s[2*c]     + __low2float(zb[c])  + sBias[ecb + 2*c]),
                                tanhfast(s[2*c + 1] + __high2float(zb[c]) + sBias[ecb + 2*c + 1]));
                        #pragma unroll
                        for (int q = 0; q < 4; q++)
                            *(uint4*)(Hbuf + eidx + q * 8) = *(uint4*)&o[q * 4];
                    }
                    __syncthreads();
                }
            }

            // ---- Z epilogue: Z^{next}_{it-1}, two half passes (before arrive!) ----
            if (doZ) {
                #pragma unroll
                for (int p = 0; p < 2; p++) {
                    if (wm == p) {
                        #pragma unroll
                        for (int i = 0; i < 4; i++)
                            #pragma unroll
                            for (int j = 0; j < 2; j++)
                                wmma::store_matrix_sync(&sC[(i * 16) * LDSC + wn * 32 + j * 16],
                                                        accZ[i][j], LDSC, wmma::mem_row_major);
                    }
                    __syncthreads();
                    {
                        int r = tid >> 1;
                        int ecb = (tid & 1) * 32;
                        int grow = m0 + p * 64 + r;
                        size_t eidx = ((size_t)(it - 1) * BATCH + grow) * UNITS + n0 + ecb;
                        const float* s = &sC[r * LDSC + ecb];
                        __nv_bfloat162 o[16];
                        #pragma unroll
                        for (int c = 0; c < 16; c++)
                            o[c] = __floats2bfloat162_rn(s[2*c], s[2*c + 1]);
                        #pragma unroll
                        for (int q = 0; q < 4; q++)
                            *(uint4*)(Zout + eidx + q * 8) = *(uint4*)&o[q * 4];
                    }
                    __syncthreads();
                }
            }
        }

        // ---- publish + gate next iteration ----
        __syncthreads();           // all h/Z stores issued block-wide
        if (tid == 0) {
            arrive_release(ctrOwn);                 // release h_it (and Z_{it-1})
            if (it < itMax) {
                unsigned ownTgt = (unsigned)(it + 1) * 8u;          // group h_it done
                while (ld_acquire(ctrOwn) < ownTgt) { }
                if (isHi && (it + 1) < SEQ) {
                    unsigned loTgt = (unsigned)(it + 3) * 8u;       // lo published Z_{it+1}
                    while (ld_acquire(ctrLo) < loTgt) { }
                }
            }
        }
        __syncthreads();
    }
}

// ---------------- head ----------------
__global__ void head(const float* __restrict__ Wo, const float* __restrict__ bo,
                     float* __restrict__ out) {
    int gt = blockIdx.x * blockDim.x + threadIdx.x;
    int w = gt >> 5, lane = gt & 31;
    if (w >= BATCH) return;
    const __nv_bfloat16* h = g_Hb + ((size_t)(SEQ - 1) * BATCH + w) * UNITS;
    float s = 0.f;
    for (int k = lane; k < UNITS; k += 32)
        s += __bfloat162float(h[k]) * Wo[k];
    #pragma unroll
    for (int o = 16; o; o >>= 1) s += __shfl_xor_sync(0xffffffffu, s, o);
    if (lane == 0) out[w] = 1.f / (1.f + expf(-(s + bo[0])));
}

// ---------------- launch ----------------
extern "C" void kernel_launch(void* const* d_in, const int* in_sizes, int n_in,
                              void* d_out, int out_size) {
    const int*   tokens = (const int*)d_in[0];
    const float* emb    = (const float*)d_in[1];
    const float* Wm[4]  = {(const float*)d_in[2],  (const float*)d_in[5],
                           (const float*)d_in[8],  (const float*)d_in[11]};
    const float* Um[4]  = {(const float*)d_in[3],  (const float*)d_in[6],
                           (const float*)d_in[9],  (const float*)d_in[12]};
    const float* bm[4]  = {(const float*)d_in[4],  (const float*)d_in[7],
                           (const float*)d_in[10], (const float*)d_in[13]};
    const float* Wo = (const float*)d_in[14];
    const float* bo = (const float*)d_in[15];
    float* out = (float*)d_out;

    cudaFuncSetAttribute(gemm0,     cudaFuncAttributeMaxDynamicSharedMemorySize, BULK_SMEM);
    cudaFuncSetAttribute(scan_pair, cudaFuncAttributeMaxDynamicSharedMemorySize, SCAN_SMEM);

    void* barAddr = nullptr;
    cudaGetSymbolAddress(&barAddr, g_arr);
    cudaMemsetAsync(barAddr, 0, 4 * 16 * 16 * sizeof(unsigned int));

    embed_kernel<<<(int)(((size_t)BT * EMBP + 255) / 256), 256>>>(tokens, emb);

    dim3 pg(1024, 8);
    prep_all<<<pg, 256>>>(Wm[0], Wm[1], Wm[2], Wm[3], Um[0], Um[1], Um[2], Um[3]);

    dim3 gin(UNITS / GBN, BT / GBM);     // (4, 1280)
    gemm0<<<gin, THREADS, BULK_SMEM>>>();

    __nv_bfloat16 *zA, *zB, *zC;
    cudaGetSymbolAddress((void**)&zA, g_Z);
    cudaGetSymbolAddress((void**)&zB, g_Zb);
    cudaGetSymbolAddress((void**)&zC, g_Zc);

    // pair 0: layers 0 (in zA, out zB) and 1 (in zB, out zC)
    scan_pair<<<256, STH, SCAN_SMEM>>>(0, bm[0], bm[1], zA, zB, zC, 1);
    // pair 1: layers 2 (in zC, out zA) and 3 (in zA, no Z out)
    scan_pair<<<256, STH, SCAN_SMEM>>>(2, bm[2], bm[3], zC, zA, zB, 0);

    head<<<(BATCH * 32 + 255) / 256, 256>>>(Wo, bo, out);
}

// round 17
// speedup vs baseline: 1.2841x; 1.0072x over previous
#include <cuda_runtime.h>
#include <cuda_bf16.h>
#include <mma.h>
#include <math.h>
#include <cstdint>

using namespace nvcuda;

#define BATCH 2048
#define SEQ   80
#define UNITS 512
#define EMB   100
#define EMBP  128
#define BT    (BATCH*SEQ)
#define THREADS 512              // gemm0 / preps
#define STH     128              // scan threads (4 warps, 2x2 of 64x32 warp tiles)

// ---- wavefront scan tiling: BM=128, BN=64, 2 CTAs/SM ----
#define BM 128
#define BN 64
#define LDSU 72                  // U / W smem stride
#define LDSA 40                  // A chunk stride (32+8)
#define LDSC 68
#define ABUF 10240               // 128*40*2
#define WBUF 4608                // 32*72*2
#define SM_U    0                // 73728
#define SM_A    73728            // 3 bufs = 30720 (sC f32 64x68x4=17408 aliases)
#define SM_W    104448           // 2 bufs = 9216
#define SM_BIAS 113664           // 256
#define SCAN_SMEM 113920

// ---- layer-0 bulk tiling ----
#define GBM 128
#define GBN 128
#define LDBB 136
#define LDBA 72
#define LDBC 132
#define BULK_ABUF 18432
#define GM_B 0
#define GM_A 139264
#define BULK_SMEM 194560

// ---------------- persistent device scratch (TIME-MAJOR slabs) ----------------
__device__ __nv_bfloat16 g_X[(size_t)BT * EMBP];
__device__ __nv_bfloat16 g_Z[(size_t)BT * UNITS];    // gemm0 out / pair1 lo in
__device__ __nv_bfloat16 g_Zb[(size_t)BT * UNITS];   // pair0 lo out = pair0 hi in
__device__ __nv_bfloat16 g_Zc[(size_t)BT * UNITS];   // pair0 hi out = pair1 lo in
__device__ __nv_bfloat16 g_Ha[(size_t)BT * UNITS];   // lo-layer h
__device__ __nv_bfloat16 g_Hb[(size_t)BT * UNITS];   // hi-layer h (head reads last slab)
__device__ __nv_bfloat16 g_W1p[EMBP * UNITS];
__device__ __nv_bfloat16 g_W[3][UNITS * UNITS];      // g_W[l] = Wm[l+1]
__device__ __nv_bfloat16 g_U[4][UNITS * UNITS];
__device__ unsigned int  g_arr[4 * 16 * 16];         // [layer][mg] counters, 64B stride

// ---------------- helpers ----------------
__device__ __forceinline__ uint32_t smem_u32(const void* p) {
    uint32_t a;
    asm("{ .reg .u64 t; cvta.to.shared.u64 t, %1; cvt.u32.u64 %0, t; }" : "=r"(a) : "l"(p));
    return a;
}
__device__ __forceinline__ void cp16(uint32_t dst, const void* src) {
    asm volatile("cp.async.cg.shared.global [%0], [%1], 16;" :: "r"(dst), "l"(src));
}
#define CP_COMMIT() asm volatile("cp.async.commit_group;" ::: "memory")
#define CP_WAIT1()  asm volatile("cp.async.wait_group 1;" ::: "memory")
#define CP_WAIT0()  asm volatile("cp.async.wait_group 0;" ::: "memory")

__device__ __forceinline__ void arrive_release(unsigned int* p) {
    asm volatile("red.release.gpu.global.add.u32 [%0], %1;" :: "l"(p), "r"(1u) : "memory");
}
__device__ __forceinline__ unsigned ld_acquire(const unsigned int* p) {
    unsigned v;
    asm volatile("ld.acquire.gpu.global.u32 %0, [%1];" : "=r"(v) : "l"(p) : "memory");
    return v;
}
__device__ __forceinline__ float tanhfast(float x) {
    float y;
    asm("tanh.approx.f32 %0, %1;" : "=f"(y) : "f"(x));
    return y;
}

// ---------------- embed + weight prep ----------------
__global__ void embed_kernel(const int* __restrict__ tokens, const float* __restrict__ emb) {
    size_t idx = (size_t)blockIdx.x * blockDim.x + threadIdx.x;
    if (idx >= (size_t)BT * EMBP) return;
    size_t row = idx >> 7;          // t*BATCH + b
    int col = (int)(idx & 127);
    int t = (int)(row >> 11);
    int b = (int)(row & 2047);
    int tok = tokens[(size_t)b * SEQ + t];
    float v = (col < EMB) ? emb[(size_t)tok * EMB + col] : 0.f;
    g_X[idx] = __float2bfloat16(v);
}

__global__ void prep_all(const float* __restrict__ W1, const float* __restrict__ W2,
                         const float* __restrict__ W3, const float* __restrict__ W4,
                         const float* __restrict__ U1, const float* __restrict__ U2,
                         const float* __restrict__ U3, const float* __restrict__ U4) {
    int y = blockIdx.y;
    int idx = blockIdx.x * blockDim.x + threadIdx.x;
    if (y == 0) {
        if (idx < EMBP * UNITS) {
            int k = idx >> 9, n = idx & 511;
            g_W1p[idx] = __float2bfloat16(k < EMB ? W1[k * UNITS + n] : 0.f);
        }
    } else if (y <= 3) {
        const float* s = (y == 1) ? W2 : (y == 2) ? W3 : W4;
        if (idx < UNITS * UNITS) g_W[y - 1][idx] = __float2bfloat16(s[idx]);
    } else {
        const float* s = (y == 4) ? U1 : (y == 5) ? U2 : (y == 6) ? U3 : U4;
        if (idx < UNITS * UNITS) g_U[y - 4][idx] = __float2bfloat16(s[idx]);
    }
}

// ---------------- layer-0 bulk GEMM: g_Z = X @ W1p ----------------
__global__ __launch_bounds__(THREADS, 1) void gemm0() {
    extern __shared__ __align__(16) unsigned char smraw[];
    __nv_bfloat16* sB = (__nv_bfloat16*)(smraw + GM_B);
    float*         sC = (float*)(smraw + GM_B);

    const __nv_bfloat16* Ag = g_X;
    const __nv_bfloat16* Bg = g_W1p;
    const int K = EMBP, aStride = EMBP, KC = 2;

    const int n0 = blockIdx.x * GBN;
    const int m0 = blockIdx.y * GBM;
    const int tid = threadIdx.x;
    const int wid = tid >> 5;
    const int wm = wid & 3, wn = wid >> 2;

    const uint32_t sbase = smem_u32(smraw);
    const uint32_t aBase = sbase + GM_A;

    for (int i = tid; i < K * 16; i += THREADS) {
        int r = i >> 4, c = i & 15;
        cp16(sbase + GM_B + r * (LDBB * 2) + c * 16, Bg + (size_t)r * UNITS + n0 + c * 8);
    }
    {
        #pragma unroll
        for (int j = 0; j < 2; j++) {
            int i = tid + j * THREADS;
            int r = i >> 3, c = i & 7;
            cp16(aBase + r * (LDBA * 2) + c * 16, Ag + (size_t)(m0 + r) * aStride + c * 8);
        }
    }
    CP_COMMIT();

    wmma::fragment<wmma::accumulator, 16, 16, 16, float> acc[2][2];
    #pragma unroll
    for (int i = 0; i < 2; i++)
        #pragma unroll
        for (int j = 0; j < 2; j++) wmma::fill_fragment(acc[i][j], 0.f);

    int buf = 0;
    for (int kc = 0; kc < KC; kc++) {
        if (kc + 1 < KC) {
            int nb = buf + 1;
            #pragma unroll
            for (int j = 0; j < 2; j++) {
                int i = tid + j * THREADS;
                int r = i >> 3, c = i & 7;
                cp16(aBase + nb * BULK_ABUF + r * (LDBA * 2) + c * 16,
                     Ag + (size_t)(m0 + r) * aStride + (kc + 1) * 64 + c * 8);
            }
            CP_COMMIT();
            CP_WAIT1();
        } else {
            CP_WAIT0();
        }
        __syncthreads();

        const __nv_bfloat16* sA = (const __nv_bfloat16*)(smraw + GM_A + buf * BULK_ABUF);
        #pragma unroll
        for (int kk = 0; kk < 64; kk += 16) {
            wmma::fragment<wmma::matrix_a, 16, 16, 16, __nv_bfloat16, wmma::row_major> a0, a1;
            wmma::fragment<wmma::matrix_b, 16, 16, 16, __nv_bfloat16, wmma::row_major> b0, b1;
            wmma::load_matrix_sync(a0, sA + (wm * 32) * LDBA + kk, LDBA);
            wmma::load_matrix_sync(a1, sA + (wm * 32 + 16) * LDBA + kk, LDBA);
            wmma::load_matrix_sync(b0, sB + (kc * 64 + kk) * LDBB + wn * 32, LDBB);
            wmma::load_matrix_sync(b1, sB + (kc * 64 + kk) * LDBB + wn * 32 + 16, LDBB);
            wmma::mma_sync(acc[0][0], a0, b0, acc[0][0]);
            wmma::mma_sync(acc[0][1], a0, b1, acc[0][1]);
            wmma::mma_sync(acc[1][0], a1, b0, acc[1][0]);
            wmma::mma_sync(acc[1][1], a1, b1, acc[1][1]);
        }
        buf++;
    }
    __syncthreads();

    #pragma unroll
    for (int i = 0; i < 2; i++)
        #pragma unroll
        for (int j = 0; j < 2; j++)
            wmma::store_matrix_sync(&sC[(wm * 32 + i * 16) * LDBC + wn * 32 + j * 16],
                                    acc[i][j], LDBC, wmma::mem_row_major);
    __syncthreads();

    {
        const int erow = tid >> 2;
        const int ecb  = (tid & 3) * 32;
        const float* s = &sC[erow * LDBC + ecb];
        __nv_bfloat162 p[16];
        #pragma unroll
        for (int q = 0; q < 16; q++) p[q] = __floats2bfloat162_rn(s[2*q], s[2*q+1]);
        __nv_bfloat16* dst = g_Z + (size_t)(m0 + erow) * UNITS + n0 + ecb;
        #pragma unroll
        for (int q = 0; q < 4; q++)
            *(uint4*)(dst + q * 8) = *(uint4*)&p[q * 4];
    }
}

// ---------------- wavefront pair scan: single-sync chunk pipeline ----------------
__global__ __launch_bounds__(STH, 2)
void scan_pair(int layerLo,
               const float* __restrict__ biasL, const float* __restrict__ biasH,
               __nv_bfloat16* zA, __nv_bfloat16* zB, __nv_bfloat16* zC,
               int hiHasZ) {
    extern __shared__ __align__(16) unsigned char smraw[];
    __nv_bfloat16* sU = (__nv_bfloat16*)(smraw + SM_U);
    float*         sC = (float*)(smraw + SM_A);     // 64x68 f32, aliases A bufs
    float*         sBias = (float*)(smraw + SM_BIAS);
    const uint32_t sbase = smem_u32(smraw);
    const uint32_t aBase = sbase + SM_A;
    const uint32_t wBase = sbase + SM_W;

    const int tid = threadIdx.x;
    const int wid = tid >> 5;
    const int bid = blockIdx.x;
    const int isHi = (bid >= 128) ? 1 : 0;
    const int lbid = bid & 127;
    const int nb = lbid & 7;
    const int mg = lbid >> 3;
    const int n0 = nb * BN;
    const int m0 = mg * BM;
    const int wm = wid & 1;          // 2 m-halves of 64
    const int wn = wid >> 1;         // 2 n-halves of 32

    const int layer = layerLo + isHi;
    const int hasZ  = isHi ? hiHasZ : 1;
    const __nv_bfloat16* Zin  = isHi ? zB : zA;
    __nv_bfloat16*       Zout = isHi ? zC : zB;
    __nv_bfloat16*       Hbuf = isHi ? g_Hb : g_Ha;
    const float*         bias = isHi ? biasH : biasL;
    const __nv_bfloat16* Wg   = hasZ ? g_W[layer] : g_W[0];

    unsigned int* ctrOwn = &g_arr[((layer) * 16 + mg) * 16];
    unsigned int* ctrLo  = &g_arr[((layerLo) * 16 + mg) * 16];

    // stage U[:, n0:n0+64] resident
    {
        const __nv_bfloat16* U = g_U[layer];
        #pragma unroll
        for (int j = 0; j < 32; j++) {
            int i = tid + j * STH;
            int r = i >> 3, c = i & 7;
            *(uint4*)&sU[r * LDSU + c * 8] = *(const uint4*)(U + (size_t)r * UNITS + n0 + c * 8);
        }
        if (tid < BN) sBias[tid] = bias[n0 + tid];
    }
    __syncthreads();
    // hi: wait for lo to publish Z_0 (lo iterations 0 and 1 done)
    if (isHi) {
        if (tid == 0) { while (ld_acquire(ctrLo) < 16u) { } }
        __syncthreads();
    }

    const int itMax = hasZ ? SEQ : (SEQ - 1);

    for (int it = 0; it <= itMax; it++) {
        const bool doRec = (it < SEQ);
        const bool doZ   = (hasZ && it >= 1);

        if (it == 0) {
            // h_0 = tanh(Z_0 + b): thread -> row tid, all 64 cols
            size_t eidx = (size_t)(m0 + tid) * UNITS + n0;
            __nv_bfloat162 zb[32];
            #pragma unroll
            for (int q = 0; q < 8; q++)
                *(uint4*)&zb[q * 4] = *(const uint4*)(Zin + eidx + q * 8);
            __nv_bfloat162 o[32];
            #pragma unroll
            for (int c = 0; c < 32; c++)
                o[c] = __floats2bfloat162_rn(tanhfast(__low2float(zb[c])  + sBias[2*c]),
                                             tanhfast(__high2float(zb[c]) + sBias[2*c + 1]));
            #pragma unroll
            for (int q = 0; q < 8; q++)
                *(uint4*)(Hbuf + eidx + q * 8) = *(uint4*)&o[q * 4];
        } else {
            // A = own h_{it-1} rows m0..m0+127
            const __nv_bfloat16* A = Hbuf + (size_t)(it - 1) * BATCH * UNITS + (size_t)m0 * UNITS;

            // prologue: C1 = {A0, W0}; C2 = {A1}
            {
                #pragma unroll
                for (int j = 0; j < 4; j++) {
                    int i = tid + j * STH;
                    int r = i >> 2, c = i & 3;
                    cp16(aBase + r * (LDSA * 2) + c * 16, A + (size_t)r * UNITS + c * 8);
                }
                if (doZ) {
                    #pragma unroll
                    for (int j = 0; j < 2; j++) {
                        int i = tid + j * STH;
                        int r = i >> 3, c = i & 7;
                        cp16(wBase + r * (LDSU * 2) + c * 16, Wg + (size_t)r * UNITS + n0 + c * 8);
                    }
                }
                CP_COMMIT();
                #pragma unroll
                for (int j = 0; j < 4; j++) {
                    int i = tid + j * STH;
                    int r = i >> 2, c = i & 3;
                    cp16(aBase + ABUF + r * (LDSA * 2) + c * 16,
                         A + (size_t)r * UNITS + 32 + c * 8);
                }
                CP_COMMIT();
            }

            wmma::fragment<wmma::accumulator, 16, 16, 16, float> accR[4][2], accZ[4][2];
            #pragma unroll
            for (int i = 0; i < 4; i++)
                #pragma unroll
                for (int j = 0; j < 2; j++) {
                    if (doRec) wmma::fill_fragment(accR[i][j], 0.f);
                    if (doZ)   wmma::fill_fragment(accZ[i][j], 0.f);
                }

            // single-sync mainloop: WAIT1 -> sync -> commit{W kc+1} -> commit{A kc+2} -> MMA kc
            for (int kc = 0; kc < 16; kc++) {
                CP_WAIT1();
                __syncthreads();            // chunk kc (A and W) landed block-wide

                // W(kc+1) -> wbuf (kc+1)&1 (readers of that buf finished before sync)
                if (doZ && (kc + 1 < 16)) {
                    int wb = (kc + 1) & 1;
                    #pragma unroll
                    for (int j = 0; j < 2; j++) {
                        int i = tid + j * STH;
                        int r = i >> 3, c = i & 7;
                        cp16(wBase + wb * WBUF + r * (LDSU * 2) + c * 16,
                             Wg + (size_t)((kc + 1) * 32 + r) * UNITS + n0 + c * 8);
                    }
                }
                CP_COMMIT();
                // A(kc+2) -> abuf (kc+2)%3 (readers = chunk kc-1, done before prior sync)
                if (kc + 2 < 16) {
                    int ab = (kc + 2) % 3;
                    #pragma unroll
                    for (int j = 0; j < 4; j++) {
                        int i = tid + j * STH;
                        int r = i >> 2, c = i & 3;
                        cp16(aBase + ab * ABUF + r * (LDSA * 2) + c * 16,
                             A + (size_t)r * UNITS + (kc + 2) * 32 + c * 8);
                    }
                }
                CP_COMMIT();

                const __nv_bfloat16* sA  = (const __nv_bfloat16*)(smraw + SM_A + (kc % 3) * ABUF);
                const __nv_bfloat16* sWc = (const __nv_bfloat16*)(smraw + SM_W + (kc & 1) * WBUF);
                #pragma unroll
                for (int kk = 0; kk < 32; kk += 16) {
                    wmma::fragment<wmma::matrix_a, 16, 16, 16, __nv_bfloat16, wmma::row_major> a[4];
                    #pragma unroll
                    for (int i = 0; i < 4; i++)
                        wmma::load_matrix_sync(a[i], sA + (wm * 64 + i * 16) * LDSA + kk, LDSA);
                    if (doRec) {
                        wmma::fragment<wmma::matrix_b, 16, 16, 16, __nv_bfloat16, wmma::row_major> b0, b1;
                        wmma::load_matrix_sync(b0, sU + (kc * 32 + kk) * LDSU + wn * 32, LDSU);
                        wmma::load_matrix_sync(b1, sU + (kc * 32 + kk) * LDSU + wn * 32 + 16, LDSU);
                        #pragma unroll
                        for (int i = 0; i < 4; i++) {
                            wmma::mma_sync(accR[i][0], a[i], b0, accR[i][0]);
                            wmma::mma_sync(accR[i][1], a[i], b1, accR[i][1]);
                        }
                    }
                    if (doZ) {
                        wmma::fragment<wmma::matrix_b, 16, 16, 16, __nv_bfloat16, wmma::row_major> c0, c1;
                        wmma::load_matrix_sync(c0, sWc + kk * LDSU + wn * 32, LDSU);
                        wmma::load_matrix_sync(c1, sWc + kk * LDSU + wn * 32 + 16, LDSU);
                        #pragma unroll
                        for (int i = 0; i < 4; i++) {
                            wmma::mma_sync(accZ[i][0], a[i], c0, accZ[i][0]);
                            wmma::mma_sync(accZ[i][1], a[i], c1, accZ[i][1]);
                        }
                    }
                }
            }
            CP_WAIT0();             // drain trailing empty groups
            __syncthreads();        // MMA done; A bufs (sC alias) free

            // ---- R epilogue: h_it = tanh(R + Z + b), two 64-row half passes ----
            if (doRec) {
                #pragma unroll
                for (int p = 0; p < 2; p++) {
                    if (wm == p) {
                        #pragma unroll
                        for (int i = 0; i < 4; i++)
                            #pragma unroll
                            for (int j = 0; j < 2; j++)
                                wmma::store_matrix_sync(&sC[(i * 16) * LDSC + wn * 32 + j * 16],
                                                        accR[i][j], LDSC, wmma::mem_row_major);
                    }
                    __syncthreads();
                    {
                        int r = tid >> 1;
                        int ecb = (tid & 1) * 32;
                        int grow = m0 + p * 64 + r;
                        size_t eidx = ((size_t)it * BATCH + grow) * UNITS + n0 + ecb;
                        __nv_bfloat162 zb[16];
                        #pragma unroll
                        for (int q = 0; q < 4; q++)
                            *(uint4*)&zb[q * 4] = *(const uint4*)(Zin + eidx + q * 8);
                        const float* s = &sC[r * LDSC + ecb];
                        __nv_bfloat162 o[16];
                        #pragma unroll
                        for (int c = 0; c < 16; c++)
                            o[c] = __floats2bfloat162_rn(
                                tanhfast(s[2*c]     + __low2float(zb[c])  + sBias[ecb + 2*c]),
                                tanhfast(s[2*c + 1] + __high2float(zb[c]) + sBias[ecb + 2*c + 1]));
                        #pragma unroll
                        for (int q = 0; q < 4; q++)
                            *(uint4*)(Hbuf + eidx + q * 8) = *(uint4*)&o[q * 4];
                    }
                    __syncthreads();
                }
            }

            // ---- Z epilogue: Z^{next}_{it-1}, before the release-arrive ----
            if (doZ) {
                #pragma unroll
                for (int p = 0; p < 2; p++) {
                    if (wm == p) {
                        #pragma unroll
                        for (int i = 0; i < 4; i++)
                            #pragma unroll
                            for (int j = 0; j < 2; j++)
                                wmma::store_matrix_sync(&sC[(i * 16) * LDSC + wn * 32 + j * 16],
                                                        accZ[i][j], LDSC, wmma::mem_row_major);
                    }
                    __syncthreads();
                    {
                        int r = tid >> 1;
                        int ecb = (tid & 1) * 32;
                        int grow = m0 + p * 64 + r;
                        size_t eidx = ((size_t)(it - 1) * BATCH + grow) * UNITS + n0 + ecb;
                        const float* s = &sC[r * LDSC + ecb];
                        __nv_bfloat162 o[16];
                        #pragma unroll
                        for (int c = 0; c < 16; c++)
                            o[c] = __floats2bfloat162_rn(s[2*c], s[2*c + 1]);
                        #pragma unroll
                        for (int q = 0; q < 4; q++)
                            *(uint4*)(Zout + eidx + q * 8) = *(uint4*)&o[q * 4];
                    }
                    __syncthreads();
                }
            }
        }

        // ---- publish + gate next iteration ----
        __syncthreads();           // all h/Z stores issued block-wide
        if (tid == 0) {
            arrive_release(ctrOwn);                 // release h_it (and Z_{it-1})
            if (it < itMax) {
                unsigned ownTgt = (unsigned)(it + 1) * 8u;          // group h_it done
                while (ld_acquire(ctrOwn) < ownTgt) { }
                if (isHi && (it + 1) < SEQ) {
                    unsigned loTgt = (unsigned)(it + 3) * 8u;       // lo published Z_{it+1}
                    while (ld_acquire(ctrLo) < loTgt) { }
                }
            }
        }
        __syncthreads();
    }
}

// ---------------- head ----------------
__global__ void head(const float* __restrict__ Wo, const float* __restrict__ bo,
                     float* __restrict__ out) {
    int gt = blockIdx.x * blockDim.x + threadIdx.x;
    int w = gt >> 5, lane = gt & 31;
    if (w >= BATCH) return;
    const __nv_bfloat16* h = g_Hb + ((size_t)(SEQ - 1) * BATCH + w) * UNITS;
    float s = 0.f;
    for (int k = lane; k < UNITS; k += 32)
        s += __bfloat162float(h[k]) * Wo[k];
    #pragma unroll
    for (int o = 16; o; o >>= 1) s += __shfl_xor_sync(0xffffffffu, s, o);
    if (lane == 0) out[w] = 1.f / (1.f + expf(-(s + bo[0])));
}

// ---------------- launch ----------------
extern "C" void kernel_launch(void* const* d_in, const int* in_sizes, int n_in,
                              void* d_out, int out_size) {
    const int*   tokens = (const int*)d_in[0];
    const float* emb    = (const float*)d_in[1];
    const float* Wm[4]  = {(const float*)d_in[2],  (const float*)d_in[5],
                           (const float*)d_in[8],  (const float*)d_in[11]};
    const float* Um[4]  = {(const float*)d_in[3],  (const float*)d_in[6],
                           (const float*)d_in[9],  (const float*)d_in[12]};
    const float* bm[4]  = {(const float*)d_in[4],  (const float*)d_in[7],
                           (const float*)d_in[10], (const float*)d_in[13]};
    const float* Wo = (const float*)d_in[14];
    const float* bo = (const float*)d_in[15];
    float* out = (float*)d_out;

    cudaFuncSetAttribute(gemm0,     cudaFuncAttributeMaxDynamicSharedMemorySize, BULK_SMEM);
    cudaFuncSetAttribute(scan_pair, cudaFuncAttributeMaxDynamicSharedMemorySize, SCAN_SMEM);

    void* barAddr = nullptr;
    cudaGetSymbolAddress(&barAddr, g_arr);
    cudaMemsetAsync(barAddr, 0, 4 * 16 * 16 * sizeof(unsigned int));

    embed_kernel<<<(int)(((size_t)BT * EMBP + 255) / 256), 256>>>(tokens, emb);

    dim3 pg(1024, 8);
    prep_all<<<pg, 256>>>(Wm[0], Wm[1], Wm[2], Wm[3], Um[0], Um[1], Um[2], Um[3]);

    dim3 gin(UNITS / GBN, BT / GBM);     // (4, 1280)
    gemm0<<<gin, THREADS, BULK_SMEM>>>();

    __nv_bfloat16 *zA, *zB, *zC;
    cudaGetSymbolAddress((void**)&zA, g_Z);
    cudaGetSymbolAddress((void**)&zB, g_Zb);
    cudaGetSymbolAddress((void**)&zC, g_Zc);

    // pair 0: layers 0 (in zA, out zB) and 1 (in zB, out zC)
    scan_pair<<<256, STH, SCAN_SMEM>>>(0, bm[0], bm[1], zA, zB, zC, 1);
    // pair 1: layers 2 (in zC, out zA) and 3 (in zA, no Z out)
    scan_pair<<<256, STH, SCAN_SMEM>>>(2, bm[2], bm[3], zC, zA, zB, 0);

    head<<<(BATCH * 32 + 255) / 256, 256>>>(Wo, bo, out);
}